// round 1
// baseline (speedup 1.0000x reference)
#include <cuda_runtime.h>

#define BATCH 16384
#define NINP  256
#define HID   1024
#define NOUT  16
#define UH    32

// Scratch activations (device globals — no runtime allocation allowed).
__device__ float g_h0[BATCH * HID];
__device__ float g_h1[BATCH * HID];

// ---------------------------------------------------------------------------
// 128x128x8 double-buffered SGEMM, 256 threads, 8x8 per-thread micro-tile.
// C = act(A @ B + bias), A: [M,K] row-major, B: [K,N] row-major.
// Requires M%128==0, N%128==0, K%8==0 (true for all our shapes).
// ---------------------------------------------------------------------------
template<bool RELU>
__global__ void __launch_bounds__(256) sgemm128(
    const float* __restrict__ A, const float* __restrict__ B,
    const float* __restrict__ bias, float* __restrict__ C,
    int M, int N, int K)
{
    __shared__ float As[2][8][128];
    __shared__ float Bs[2][8][128];

    const int tid = threadIdx.x;
    const int bm = blockIdx.y * 128;
    const int bn = blockIdx.x * 128;

    // A tile load: 128 rows x 8 cols, one float4 per thread.
    const int a_row = tid >> 1;
    const int a_col = (tid & 1) << 2;
    // B tile load: 8 rows x 128 cols, one float4 per thread.
    const int b_row = tid >> 5;
    const int b_col = (tid & 31) << 2;

    const float* Ap = A + (size_t)(bm + a_row) * K + a_col;
    const float* Bp = B + (size_t)b_row * N + bn + b_col;

    const int tx = tid & 15;
    const int ty = tid >> 4;

    float acc[8][8];
#pragma unroll
    for (int i = 0; i < 8; i++)
#pragma unroll
        for (int j = 0; j < 8; j++) acc[i][j] = 0.f;

    // prologue: load k-tile 0
    float4 a4 = *(const float4*)Ap;
    float4 b4 = *(const float4*)Bp;
    As[0][a_col + 0][a_row] = a4.x;
    As[0][a_col + 1][a_row] = a4.y;
    As[0][a_col + 2][a_row] = a4.z;
    As[0][a_col + 3][a_row] = a4.w;
    *(float4*)&Bs[0][b_row][b_col] = b4;
    __syncthreads();

    const int nk = K >> 3;
    for (int kt = 0; kt < nk; kt++) {
        const int cur = kt & 1;
        const int nxt = cur ^ 1;
        if (kt + 1 < nk) {
            a4 = *(const float4*)(Ap + (kt + 1) * 8);
            b4 = *(const float4*)(Bp + (size_t)(kt + 1) * 8 * N);
        }
#pragma unroll
        for (int k = 0; k < 8; k++) {
            float4 x0 = *(const float4*)&As[cur][k][ty * 4];
            float4 x1 = *(const float4*)&As[cur][k][ty * 4 + 64];
            float4 y0 = *(const float4*)&Bs[cur][k][tx * 4];
            float4 y1 = *(const float4*)&Bs[cur][k][tx * 4 + 64];
            float av[8] = {x0.x, x0.y, x0.z, x0.w, x1.x, x1.y, x1.z, x1.w};
            float bv[8] = {y0.x, y0.y, y0.z, y0.w, y1.x, y1.y, y1.z, y1.w};
#pragma unroll
            for (int i = 0; i < 8; i++)
#pragma unroll
                for (int j = 0; j < 8; j++)
                    acc[i][j] += av[i] * bv[j];
        }
        if (kt + 1 < nk) {
            As[nxt][a_col + 0][a_row] = a4.x;
            As[nxt][a_col + 1][a_row] = a4.y;
            As[nxt][a_col + 2][a_row] = a4.z;
            As[nxt][a_col + 3][a_row] = a4.w;
            *(float4*)&Bs[nxt][b_row][b_col] = b4;
        }
        __syncthreads();
    }

    // epilogue: bias + optional ReLU, vectorized stores
#pragma unroll
    for (int ih = 0; ih < 2; ih++) {
#pragma unroll
        for (int i = 0; i < 4; i++) {
            int r = bm + ih * 64 + ty * 4 + i;
#pragma unroll
            for (int jh = 0; jh < 2; jh++) {
                int c = bn + jh * 64 + tx * 4;
                float4 v;
                v.x = acc[ih * 4 + i][jh * 4 + 0] + bias[c + 0];
                v.y = acc[ih * 4 + i][jh * 4 + 1] + bias[c + 1];
                v.z = acc[ih * 4 + i][jh * 4 + 2] + bias[c + 2];
                v.w = acc[ih * 4 + i][jh * 4 + 3] + bias[c + 3];
                if (RELU) {
                    v.x = fmaxf(v.x, 0.f);
                    v.y = fmaxf(v.y, 0.f);
                    v.z = fmaxf(v.z, 0.f);
                    v.w = fmaxf(v.w, 0.f);
                }
                *(float4*)&C[(size_t)r * N + c] = v;
            }
        }
    }
}

// ---------------------------------------------------------------------------
// Output layer: out[b,o] = H1[b,:] . W2[:,o] + b2[o]  (N=16, thin GEMM)
// One thread per output element. W2 (64KB) is L1-resident; H1 rows broadcast.
// ---------------------------------------------------------------------------
__global__ void __launch_bounds__(256) gemm_out(
    const float* __restrict__ Hin, const float* __restrict__ W2,
    const float* __restrict__ b2, float* __restrict__ out)
{
    const int idx = blockIdx.x * 256 + threadIdx.x;
    const int b = idx >> 4;
    const int o = idx & 15;
    const float* h = Hin + (size_t)b * HID;
    float acc = b2[o];
#pragma unroll 8
    for (int k = 0; k < HID; k++)
        acc = fmaf(h[k], W2[k * NOUT + o], acc);
    out[idx] = acc;
}

// ---------------------------------------------------------------------------
// Per-feature univariate MLPs: 1 -> 32 -> 32 -> 16, summed over features.
// One thread per batch row; weights per feature staged in SMEM and read with
// broadcast LDS.128 (1 shared load per 4 FFMA). Feature axis split into
// UNI_CHUNKS chunks (grid.y) for occupancy; partials merged via atomicAdd
// (runs after gemm_out has written the main-MLP result).
// ---------------------------------------------------------------------------
#define UNI_CHUNKS 4
#define UNI_FEATS  (NINP / UNI_CHUNKS)   // 64 features per block

__global__ void __launch_bounds__(256) uni_kernel(
    const float* __restrict__ x,
    const float* __restrict__ uw1, const float* __restrict__ ub1,
    const float* __restrict__ uw2, const float* __restrict__ ub2,
    const float* __restrict__ uw3, const float* __restrict__ ub3,
    float* __restrict__ out)
{
    __shared__ float w1s[UH];
    __shared__ float b1s[UH];
    __shared__ float b2s[UH];
    __shared__ float b3s[NOUT];
    __shared__ float w2s[UH * UH];
    __shared__ float w3s[UH * NOUT];

    const int tid = threadIdx.x;
    const int b = blockIdx.x * 256 + tid;
    const int i0 = blockIdx.y * UNI_FEATS;

    float acc[NOUT];
#pragma unroll
    for (int o = 0; o < NOUT; o++) acc[o] = 0.f;

    for (int ii = 0; ii < UNI_FEATS; ii++) {
        const int i = i0 + ii;
        // cooperative weight staging
        if (tid < UH) {
            w1s[tid] = uw1[i * UH + tid];
            b1s[tid] = ub1[i * UH + tid];
            b2s[tid] = ub2[i * UH + tid];
        }
        if (tid >= 32 && tid < 32 + NOUT)
            b3s[tid - 32] = ub3[i * NOUT + (tid - 32)];
#pragma unroll
        for (int t = 0; t < UH * UH / 256; t++)
            w2s[t * 256 + tid] = uw2[(size_t)i * UH * UH + t * 256 + tid];
#pragma unroll
        for (int t = 0; t < UH * NOUT / 256; t++)
            w3s[t * 256 + tid] = uw3[(size_t)i * UH * NOUT + t * 256 + tid];
        __syncthreads();

        const float xb = x[(size_t)b * NINP + i];

        // layer 1: 1 -> 32
        float h1[UH];
#pragma unroll
        for (int j = 0; j < UH; j++)
            h1[j] = fmaxf(fmaf(xb, w1s[j], b1s[j]), 0.f);

        // layer 2: 32 -> 32
        float h2[UH];
#pragma unroll
        for (int j = 0; j < UH; j++) h2[j] = b2s[j];
#pragma unroll
        for (int f = 0; f < UH; f++) {
            const float hf = h1[f];
#pragma unroll
            for (int j4 = 0; j4 < UH / 4; j4++) {
                float4 w = *(const float4*)&w2s[f * UH + j4 * 4];
                h2[j4 * 4 + 0] = fmaf(hf, w.x, h2[j4 * 4 + 0]);
                h2[j4 * 4 + 1] = fmaf(hf, w.y, h2[j4 * 4 + 1]);
                h2[j4 * 4 + 2] = fmaf(hf, w.z, h2[j4 * 4 + 2]);
                h2[j4 * 4 + 3] = fmaf(hf, w.w, h2[j4 * 4 + 3]);
            }
        }
#pragma unroll
        for (int j = 0; j < UH; j++) h2[j] = fmaxf(h2[j], 0.f);

        // layer 3: 32 -> 16, accumulate (bias added once per feature)
#pragma unroll
        for (int o = 0; o < NOUT; o++) acc[o] += b3s[o];
#pragma unroll
        for (int f = 0; f < UH; f++) {
            const float hf = h2[f];
#pragma unroll
            for (int o4 = 0; o4 < NOUT / 4; o4++) {
                float4 w = *(const float4*)&w3s[f * NOUT + o4 * 4];
                acc[o4 * 4 + 0] = fmaf(hf, w.x, acc[o4 * 4 + 0]);
                acc[o4 * 4 + 1] = fmaf(hf, w.y, acc[o4 * 4 + 1]);
                acc[o4 * 4 + 2] = fmaf(hf, w.z, acc[o4 * 4 + 2]);
                acc[o4 * 4 + 3] = fmaf(hf, w.w, acc[o4 * 4 + 3]);
            }
        }
        __syncthreads();
    }

#pragma unroll
    for (int o = 0; o < NOUT; o++)
        atomicAdd(&out[(size_t)b * NOUT + o], acc[o]);
}

// ---------------------------------------------------------------------------
extern "C" void kernel_launch(void* const* d_in, const int* in_sizes, int n_in,
                              void* d_out, int out_size)
{
    const float* x   = (const float*)d_in[0];
    const float* W0  = (const float*)d_in[1];
    const float* b0  = (const float*)d_in[2];
    const float* W1  = (const float*)d_in[3];
    const float* b1  = (const float*)d_in[4];
    const float* W2  = (const float*)d_in[5];
    const float* b2  = (const float*)d_in[6];
    const float* uw1 = (const float*)d_in[7];
    const float* ub1 = (const float*)d_in[8];
    const float* uw2 = (const float*)d_in[9];
    const float* ub2 = (const float*)d_in[10];
    const float* uw3 = (const float*)d_in[11];
    const float* ub3 = (const float*)d_in[12];
    float* out = (float*)d_out;

    float* h0;
    float* h1;
    cudaGetSymbolAddress((void**)&h0, g_h0);
    cudaGetSymbolAddress((void**)&h1, g_h1);

    // layer 0: [16384,256] @ [256,1024] + b0, ReLU
    {
        dim3 grid(HID / 128, BATCH / 128);
        sgemm128<true><<<grid, 256>>>(x, W0, b0, h0, BATCH, HID, NINP);
    }
    // layer 1: [16384,1024] @ [1024,1024] + b1, ReLU
    {
        dim3 grid(HID / 128, BATCH / 128);
        sgemm128<true><<<grid, 256>>>(h0, W1, b1, h1, BATCH, HID, HID);
    }
    // layer 2: [16384,1024] @ [1024,16] + b2 -> out (writes every element)
    gemm_out<<<(BATCH * NOUT) / 256, 256>>>(h1, W2, b2, out);

    // uni MLPs accumulate on top of out
    {
        dim3 grid(BATCH / 256, UNI_CHUNKS);
        uni_kernel<<<grid, 256>>>(x, uw1, ub1, uw2, ub2, uw3, ub3, out);
    }
}

// round 5
// speedup vs baseline: 1.8522x; 1.8522x over previous
#include <cuda_runtime.h>
#include <cstdint>

#define BATCH 16384
#define NINP  256
#define HID   1024
#define NOUT  16
#define UH    32

// ---------------------------------------------------------------------------
// Device scratch (no runtime allocation allowed)
// ---------------------------------------------------------------------------
__device__ float g_h0[BATCH * HID];
__device__ float g_h1[BATCH * HID];
__device__ float g_x[BATCH * NINP];   // x pre-rounded to tf32
__device__ float g_w0t[HID * NINP];   // W0^T [HID][NINP], tf32-rounded
__device__ float g_w1t[HID * HID];    // W1^T, tf32-rounded

// ---------------------------------------------------------------------------
// Helpers
// ---------------------------------------------------------------------------
__device__ __forceinline__ uint32_t smem_u32(const void* p) {
    uint32_t a;
    asm("{ .reg .u64 t; cvta.to.shared.u64 t, %1; cvt.u32.u64 %0, t; }"
        : "=r"(a) : "l"(p));
    return a;
}

// tf32 destination is a .b32 register (storage format), per PTX ISA.
__device__ __forceinline__ float to_tf32(float x) {
    uint32_t r;
    asm("cvt.rna.tf32.f32 %0, %1;" : "=r"(r) : "f"(x));
    return __uint_as_float(r);
}

#define CP_ASYNC16(dst_u32, src_ptr) \
    asm volatile("cp.async.cg.shared.global [%0], [%1], 16;" \
        :: "r"(dst_u32), "l"(src_ptr))
#define CP_COMMIT() asm volatile("cp.async.commit_group;")
#define CP_WAIT(n)  asm volatile("cp.async.wait_group %0;" :: "n"(n))

__device__ __forceinline__ void mma_tf32(
    float& d0, float& d1, float& d2, float& d3,
    uint32_t a0, uint32_t a1, uint32_t a2, uint32_t a3,
    uint32_t b0, uint32_t b1)
{
    asm volatile(
        "mma.sync.aligned.m16n8k8.row.col.f32.tf32.tf32.f32 "
        "{%0,%1,%2,%3}, {%4,%5,%6,%7}, {%8,%9}, {%0,%1,%2,%3};"
        : "+f"(d0), "+f"(d1), "+f"(d2), "+f"(d3)
        : "r"(a0), "r"(a1), "r"(a2), "r"(a3), "r"(b0), "r"(b1));
}

// ---------------------------------------------------------------------------
// tf32 mma.sync GEMM: C[M,N] = act(A[M,K] @ W[K,N] + bias)
// A row-major (pre-rounded tf32); BT = W^T [N][K] row-major (pre-rounded).
// CTA 128x256x32, 256 threads, 8 warps (2x4), warp tile 64x64.
// cp.async 2-stage double buffer; padded smem stride 36 (conflict-free).
// ---------------------------------------------------------------------------
#define BM 128
#define BN 256
#define BK 32
#define ASTR 36
#define AS_FLOATS (BM * ASTR)              // 4608
#define BS_FLOATS (BN * ASTR)              // 9216
#define STG_FLOATS (AS_FLOATS + BS_FLOATS) // 13824
#define GEMM_SMEM ((BN + 2 * STG_FLOATS) * 4)   // 111616 B

__global__ void __launch_bounds__(256, 1) mma_gemm(
    const float* __restrict__ A, const float* __restrict__ BT,
    const float* __restrict__ bias, float* __restrict__ C,
    int K, int Ntot, int relu, int roundout)
{
    extern __shared__ float sm[];
    float* bias_s = sm;
    float* stage0 = sm + BN;
    const uint32_t stage0_u32 = smem_u32(stage0);

    const int tid = threadIdx.x;
    const int lane = tid & 31;
    const int wid = tid >> 5;
    const int wr = wid >> 2;          // 0..1  (warp row, 64 rows each)
    const int wc = wid & 3;           // 0..3  (warp col, 64 cols each)
    const int m0 = blockIdx.y * BM;
    const int n0 = blockIdx.x * BN;

    if (tid < BN) bias_s[tid] = bias[n0 + tid];

    const int r = lane >> 2;          // 0..7
    const int c = lane & 3;           // 0..3

    float acc[4][8][4];
#pragma unroll
    for (int mt = 0; mt < 4; mt++)
#pragma unroll
        for (int nt = 0; nt < 8; nt++)
#pragma unroll
            for (int j = 0; j < 4; j++) acc[mt][nt][j] = 0.f;

    const int T = K / BK;

    // ---- async tile loader ----
    auto issue = [&](int t) {
        const uint32_t su = stage0_u32 + (uint32_t)((t & 1) * STG_FLOATS) * 4u;
#pragma unroll
        for (int i = 0; i < 4; i++) {                 // A: 128 rows x 8 quads
            const int q = tid + i * 256;
            const int row = q >> 3, qq = q & 7;
            CP_ASYNC16(su + (uint32_t)(row * ASTR + qq * 4) * 4u,
                       A + (size_t)(m0 + row) * K + t * BK + qq * 4);
        }
        const uint32_t bu = su + AS_FLOATS * 4u;
#pragma unroll
        for (int i = 0; i < 8; i++) {                 // B: 256 rows x 8 quads
            const int q = tid + i * 256;
            const int row = q >> 3, qq = q & 7;
            CP_ASYNC16(bu + (uint32_t)(row * ASTR + qq * 4) * 4u,
                       BT + (size_t)(n0 + row) * K + t * BK + qq * 4);
        }
    };

    issue(0);
    CP_COMMIT();

    for (int t = 0; t < T; t++) {
        if (t + 1 < T) {
            issue(t + 1);
            CP_COMMIT();
            CP_WAIT(1);
        } else {
            CP_WAIT(0);
        }
        __syncthreads();

        const float* As = stage0 + (t & 1) * STG_FLOATS;
        const float* Bs = As + AS_FLOATS;

#pragma unroll
        for (int kk = 0; kk < 4; kk++) {
            uint32_t af[4][4];
#pragma unroll
            for (int mt = 0; mt < 4; mt++) {
                const int mb = wr * 64 + mt * 16;
                af[mt][0] = *(const uint32_t*)&As[(mb + r) * ASTR + kk * 8 + c];
                af[mt][1] = *(const uint32_t*)&As[(mb + r + 8) * ASTR + kk * 8 + c];
                af[mt][2] = *(const uint32_t*)&As[(mb + r) * ASTR + kk * 8 + c + 4];
                af[mt][3] = *(const uint32_t*)&As[(mb + r + 8) * ASTR + kk * 8 + c + 4];
            }
            uint32_t bf[8][2];
#pragma unroll
            for (int nt = 0; nt < 8; nt++) {
                const int bn = wc * 64 + nt * 8 + r;
                bf[nt][0] = *(const uint32_t*)&Bs[bn * ASTR + kk * 8 + c];
                bf[nt][1] = *(const uint32_t*)&Bs[bn * ASTR + kk * 8 + c + 4];
            }
#pragma unroll
            for (int mt = 0; mt < 4; mt++)
#pragma unroll
                for (int nt = 0; nt < 8; nt++)
                    mma_tf32(acc[mt][nt][0], acc[mt][nt][1],
                             acc[mt][nt][2], acc[mt][nt][3],
                             af[mt][0], af[mt][1], af[mt][2], af[mt][3],
                             bf[nt][0], bf[nt][1]);
        }
        __syncthreads();
    }

    // ---- epilogue: bias + ReLU (+ tf32 round), float2 stores ----
#pragma unroll
    for (int mt = 0; mt < 4; mt++) {
        const int row0 = m0 + wr * 64 + mt * 16 + r;
#pragma unroll
        for (int nt = 0; nt < 8; nt++) {
            const int col = n0 + wc * 64 + nt * 8 + c * 2;
            const float bx = bias_s[wc * 64 + nt * 8 + c * 2];
            const float by = bias_s[wc * 64 + nt * 8 + c * 2 + 1];
            float v0 = acc[mt][nt][0] + bx;
            float v1 = acc[mt][nt][1] + by;
            float v2 = acc[mt][nt][2] + bx;
            float v3 = acc[mt][nt][3] + by;
            if (relu) {
                v0 = fmaxf(v0, 0.f); v1 = fmaxf(v1, 0.f);
                v2 = fmaxf(v2, 0.f); v3 = fmaxf(v3, 0.f);
            }
            if (roundout) {
                v0 = to_tf32(v0); v1 = to_tf32(v1);
                v2 = to_tf32(v2); v3 = to_tf32(v3);
            }
            *(float2*)&C[(size_t)row0 * Ntot + col] = make_float2(v0, v1);
            *(float2*)&C[(size_t)(row0 + 8) * Ntot + col] = make_float2(v2, v3);
        }
    }
}

// ---------------------------------------------------------------------------
// x -> tf32-rounded copy (float4)
// ---------------------------------------------------------------------------
__global__ void __launch_bounds__(256) cvt_x(
    const float* __restrict__ in, float* __restrict__ outp, int n4)
{
    const int i = blockIdx.x * 256 + threadIdx.x;
    if (i < n4) {
        float4 v = ((const float4*)in)[i];
        v.x = to_tf32(v.x); v.y = to_tf32(v.y);
        v.z = to_tf32(v.z); v.w = to_tf32(v.w);
        ((float4*)outp)[i] = v;
    }
}

// ---------------------------------------------------------------------------
// W[K][N] -> WT[N][K] tiled transpose with tf32 rounding
// ---------------------------------------------------------------------------
__global__ void __launch_bounds__(256) transpose_cvt(
    const float* __restrict__ W, float* __restrict__ WT, int K, int N)
{
    __shared__ float t[32][33];
    const int bx = blockIdx.x * 32;   // n
    const int by = blockIdx.y * 32;   // k
    const int x = threadIdx.x & 31;
    const int y = threadIdx.x >> 5;   // 0..7
#pragma unroll
    for (int i = 0; i < 32; i += 8)
        t[y + i][x] = to_tf32(W[(size_t)(by + y + i) * N + bx + x]);
    __syncthreads();
#pragma unroll
    for (int i = 0; i < 32; i += 8)
        WT[(size_t)(bx + y + i) * K + by + x] = t[x][y + i];
}

// ---------------------------------------------------------------------------
// Output layer: out[b][o] = H1[b,:] . W2[:,o] + b2[o]; 4 outputs per thread.
// ---------------------------------------------------------------------------
__global__ void __launch_bounds__(256) gemm_out(
    const float* __restrict__ Hin, const float* __restrict__ W2,
    const float* __restrict__ b2, float* __restrict__ out)
{
    const int idx = blockIdx.x * 256 + threadIdx.x;   // BATCH*4 total
    const int b = idx >> 2;
    const int og = (idx & 3) * 4;
    const float* h = Hin + (size_t)b * HID;
    float4 acc = *(const float4*)(b2 + og);
#pragma unroll 4
    for (int k = 0; k < HID; k++) {
        const float hv = h[k];
        const float4 w = *(const float4*)(W2 + k * NOUT + og);
        acc.x = fmaf(hv, w.x, acc.x);
        acc.y = fmaf(hv, w.y, acc.y);
        acc.z = fmaf(hv, w.z, acc.z);
        acc.w = fmaf(hv, w.w, acc.w);
    }
    *(float4*)(out + (size_t)b * NOUT + og) = acc;
}

// ---------------------------------------------------------------------------
// Per-feature univariate MLPs, 2 batch rows per thread (halves LDS per FFMA).
// ---------------------------------------------------------------------------
#define UNI_CHUNKS 8
#define UNI_FEATS  (NINP / UNI_CHUNKS)   // 32 features per block

__global__ void __launch_bounds__(256) uni_kernel(
    const float* __restrict__ x,
    const float* __restrict__ uw1, const float* __restrict__ ub1,
    const float* __restrict__ uw2, const float* __restrict__ ub2,
    const float* __restrict__ uw3, const float* __restrict__ ub3,
    float* __restrict__ out)
{
    __shared__ float w1s[UH];
    __shared__ float b1s[UH];
    __shared__ float b2s[UH];
    __shared__ float b3s[NOUT];
    __shared__ float w2s[UH * UH];
    __shared__ float w3s[UH * NOUT];

    const int tid = threadIdx.x;
    const int ba = blockIdx.x * 512 + tid;
    const int bb = ba + 256;
    const int i0 = blockIdx.y * UNI_FEATS;

    float acc0[NOUT], acc1[NOUT];
#pragma unroll
    for (int o = 0; o < NOUT; o++) { acc0[o] = 0.f; acc1[o] = 0.f; }

    for (int ii = 0; ii < UNI_FEATS; ii++) {
        const int i = i0 + ii;
        if (tid < UH) {
            w1s[tid] = uw1[i * UH + tid];
            b1s[tid] = ub1[i * UH + tid];
            b2s[tid] = ub2[i * UH + tid];
        }
        if (tid >= 32 && tid < 32 + NOUT)
            b3s[tid - 32] = ub3[i * NOUT + (tid - 32)];
#pragma unroll
        for (int t = 0; t < UH * UH / 256; t++)
            w2s[t * 256 + tid] = uw2[(size_t)i * UH * UH + t * 256 + tid];
#pragma unroll
        for (int t = 0; t < UH * NOUT / 256; t++)
            w3s[t * 256 + tid] = uw3[(size_t)i * UH * NOUT + t * 256 + tid];
        __syncthreads();

        const float xa = x[(size_t)ba * NINP + i];
        const float xb = x[(size_t)bb * NINP + i];

        float h1a[UH], h1b[UH];
#pragma unroll
        for (int j = 0; j < UH; j++) {
            h1a[j] = fmaxf(fmaf(xa, w1s[j], b1s[j]), 0.f);
            h1b[j] = fmaxf(fmaf(xb, w1s[j], b1s[j]), 0.f);
        }

        float h2a[UH], h2b[UH];
#pragma unroll
        for (int j = 0; j < UH; j++) { h2a[j] = b2s[j]; h2b[j] = b2s[j]; }
#pragma unroll
        for (int f = 0; f < UH; f++) {
            const float fa = h1a[f];
            const float fb = h1b[f];
#pragma unroll
            for (int j4 = 0; j4 < UH / 4; j4++) {
                const float4 w = *(const float4*)&w2s[f * UH + j4 * 4];
                h2a[j4 * 4 + 0] = fmaf(fa, w.x, h2a[j4 * 4 + 0]);
                h2a[j4 * 4 + 1] = fmaf(fa, w.y, h2a[j4 * 4 + 1]);
                h2a[j4 * 4 + 2] = fmaf(fa, w.z, h2a[j4 * 4 + 2]);
                h2a[j4 * 4 + 3] = fmaf(fa, w.w, h2a[j4 * 4 + 3]);
                h2b[j4 * 4 + 0] = fmaf(fb, w.x, h2b[j4 * 4 + 0]);
                h2b[j4 * 4 + 1] = fmaf(fb, w.y, h2b[j4 * 4 + 1]);
                h2b[j4 * 4 + 2] = fmaf(fb, w.z, h2b[j4 * 4 + 2]);
                h2b[j4 * 4 + 3] = fmaf(fb, w.w, h2b[j4 * 4 + 3]);
            }
        }
#pragma unroll
        for (int j = 0; j < UH; j++) {
            h2a[j] = fmaxf(h2a[j], 0.f);
            h2b[j] = fmaxf(h2b[j], 0.f);
        }

#pragma unroll
        for (int o = 0; o < NOUT; o++) { acc0[o] += b3s[o]; acc1[o] += b3s[o]; }
#pragma unroll
        for (int f = 0; f < UH; f++) {
            const float fa = h2a[f];
            const float fb = h2b[f];
#pragma unroll
            for (int o4 = 0; o4 < NOUT / 4; o4++) {
                const float4 w = *(const float4*)&w3s[f * NOUT + o4 * 4];
                acc0[o4 * 4 + 0] = fmaf(fa, w.x, acc0[o4 * 4 + 0]);
                acc0[o4 * 4 + 1] = fmaf(fa, w.y, acc0[o4 * 4 + 1]);
                acc0[o4 * 4 + 2] = fmaf(fa, w.z, acc0[o4 * 4 + 2]);
                acc0[o4 * 4 + 3] = fmaf(fa, w.w, acc0[o4 * 4 + 3]);
                acc1[o4 * 4 + 0] = fmaf(fb, w.x, acc1[o4 * 4 + 0]);
                acc1[o4 * 4 + 1] = fmaf(fb, w.y, acc1[o4 * 4 + 1]);
                acc1[o4 * 4 + 2] = fmaf(fb, w.z, acc1[o4 * 4 + 2]);
                acc1[o4 * 4 + 3] = fmaf(fb, w.w, acc1[o4 * 4 + 3]);
            }
        }
        __syncthreads();
    }

#pragma unroll
    for (int o = 0; o < NOUT; o++) {
        atomicAdd(&out[(size_t)ba * NOUT + o], acc0[o]);
        atomicAdd(&out[(size_t)bb * NOUT + o], acc1[o]);
    }
}

// ---------------------------------------------------------------------------
extern "C" void kernel_launch(void* const* d_in, const int* in_sizes, int n_in,
                              void* d_out, int out_size)
{
    const float* x   = (const float*)d_in[0];
    const float* W0  = (const float*)d_in[1];
    const float* b0  = (const float*)d_in[2];
    const float* W1  = (const float*)d_in[3];
    const float* b1  = (const float*)d_in[4];
    const float* W2  = (const float*)d_in[5];
    const float* b2  = (const float*)d_in[6];
    const float* uw1 = (const float*)d_in[7];
    const float* ub1 = (const float*)d_in[8];
    const float* uw2 = (const float*)d_in[9];
    const float* ub2 = (const float*)d_in[10];
    const float* uw3 = (const float*)d_in[11];
    const float* ub3 = (const float*)d_in[12];
    float* out = (float*)d_out;

    float *h0, *h1, *xr, *w0t, *w1t;
    cudaGetSymbolAddress((void**)&h0, g_h0);
    cudaGetSymbolAddress((void**)&h1, g_h1);
    cudaGetSymbolAddress((void**)&xr, g_x);
    cudaGetSymbolAddress((void**)&w0t, g_w0t);
    cudaGetSymbolAddress((void**)&w1t, g_w1t);

    cudaFuncSetAttribute(mma_gemm, cudaFuncAttributeMaxDynamicSharedMemorySize, GEMM_SMEM);

    // prep: round x, transpose+round weights
    cvt_x<<<(BATCH * NINP / 4 + 255) / 256, 256>>>(x, xr, BATCH * NINP / 4);
    {
        dim3 g0(HID / 32, NINP / 32);
        transpose_cvt<<<g0, 256>>>(W0, w0t, NINP, HID);
        dim3 g1(HID / 32, HID / 32);
        transpose_cvt<<<g1, 256>>>(W1, w1t, HID, HID);
    }

    // layer 0: h0 = round_tf32(relu(x @ W0 + b0))
    {
        dim3 grid(HID / BN, BATCH / BM);
        mma_gemm<<<grid, 256, GEMM_SMEM>>>(xr, w0t, b0, h0, NINP, HID, 1, 1);
    }
    // layer 1: h1 = relu(h0 @ W1 + b1)
    {
        dim3 grid(HID / BN, BATCH / BM);
        mma_gemm<<<grid, 256, GEMM_SMEM>>>(h0, w1t, b1, h1, HID, HID, 1, 0);
    }
    // layer 2: out = h1 @ W2 + b2
    gemm_out<<<(BATCH * 4) / 256, 256>>>(h1, W2, b2, out);

    // uni MLPs accumulate on top of out
    {
        dim3 grid(BATCH / 512, UNI_CHUNKS);
        uni_kernel<<<grid, 256>>>(x, uw1, ub1, uw2, ub2, uw3, ub3, out);
    }
}

// round 7
// speedup vs baseline: 2.2597x; 1.2200x over previous
#include <cuda_runtime.h>
#include <cstdint>

#define BATCH 16384
#define NINP  256
#define HID   1024
#define NOUT  16
#define UH    32

// ---------------------------------------------------------------------------
// Device scratch (no runtime allocation allowed)
// ---------------------------------------------------------------------------
__device__ float g_h0[BATCH * HID];
__device__ float g_h1[BATCH * HID];
__device__ float g_x[BATCH * NINP];    // x pre-rounded to tf32 (main GEMM A)
__device__ float g_w0t[HID * NINP];    // W0^T [HID][NINP], tf32-rounded
__device__ float g_w1t[HID * HID];     // W1^T, tf32-rounded
__device__ float g_uw2t[NINP * UH * UH];    // per-feature w2^T [i][fo][fi], tf32
__device__ float g_uw3t[NINP * UH * NOUT];  // per-feature w3^T [i][fo][fi], tf32

// ---------------------------------------------------------------------------
// Helpers
// ---------------------------------------------------------------------------
__device__ __forceinline__ uint32_t smem_u32(const void* p) {
    uint32_t a;
    asm("{ .reg .u64 t; cvta.to.shared.u64 t, %1; cvt.u32.u64 %0, t; }"
        : "=r"(a) : "l"(p));
    return a;
}

// tf32 destination is a .b32 register (storage format), per PTX ISA.
__device__ __forceinline__ float to_tf32(float x) {
    uint32_t r;
    asm("cvt.rna.tf32.f32 %0, %1;" : "=r"(r) : "f"(x));
    return __uint_as_float(r);
}

#define CP_ASYNC16(dst_u32, src_ptr) \
    asm volatile("cp.async.cg.shared.global [%0], [%1], 16;" \
        :: "r"(dst_u32), "l"(src_ptr))
#define CP_COMMIT() asm volatile("cp.async.commit_group;")
#define CP_WAIT(n)  asm volatile("cp.async.wait_group %0;" :: "n"(n))

__device__ __forceinline__ void mma_tf32(
    float& d0, float& d1, float& d2, float& d3,
    uint32_t a0, uint32_t a1, uint32_t a2, uint32_t a3,
    uint32_t b0, uint32_t b1)
{
    asm volatile(
        "mma.sync.aligned.m16n8k8.row.col.f32.tf32.tf32.f32 "
        "{%0,%1,%2,%3}, {%4,%5,%6,%7}, {%8,%9}, {%0,%1,%2,%3};"
        : "+f"(d0), "+f"(d1), "+f"(d2), "+f"(d3)
        : "r"(a0), "r"(a1), "r"(a2), "r"(a3), "r"(b0), "r"(b1));
}

// ---------------------------------------------------------------------------
// tf32 mma.sync GEMM: C[M,N] = act(A[M,K] @ W[K,N] + bias)   (unchanged R5)
// ---------------------------------------------------------------------------
#define BM 128
#define BN 256
#define BK 32
#define ASTR 36
#define AS_FLOATS (BM * ASTR)
#define BS_FLOATS (BN * ASTR)
#define STG_FLOATS (AS_FLOATS + BS_FLOATS)
#define GEMM_SMEM ((BN + 2 * STG_FLOATS) * 4)

__global__ void __launch_bounds__(256, 1) mma_gemm(
    const float* __restrict__ A, const float* __restrict__ BT,
    const float* __restrict__ bias, float* __restrict__ C,
    int K, int Ntot, int relu, int roundout)
{
    extern __shared__ float sm[];
    float* bias_s = sm;
    float* stage0 = sm + BN;
    const uint32_t stage0_u32 = smem_u32(stage0);

    const int tid = threadIdx.x;
    const int lane = tid & 31;
    const int wid = tid >> 5;
    const int wr = wid >> 2;
    const int wc = wid & 3;
    const int m0 = blockIdx.y * BM;
    const int n0 = blockIdx.x * BN;

    if (tid < BN) bias_s[tid] = bias[n0 + tid];

    const int r = lane >> 2;
    const int c = lane & 3;

    float acc[4][8][4];
#pragma unroll
    for (int mt = 0; mt < 4; mt++)
#pragma unroll
        for (int nt = 0; nt < 8; nt++)
#pragma unroll
            for (int j = 0; j < 4; j++) acc[mt][nt][j] = 0.f;

    const int T = K / BK;

    auto issue = [&](int t) {
        const uint32_t su = stage0_u32 + (uint32_t)((t & 1) * STG_FLOATS) * 4u;
#pragma unroll
        for (int i = 0; i < 4; i++) {
            const int q = tid + i * 256;
            const int row = q >> 3, qq = q & 7;
            CP_ASYNC16(su + (uint32_t)(row * ASTR + qq * 4) * 4u,
                       A + (size_t)(m0 + row) * K + t * BK + qq * 4);
        }
        const uint32_t bu = su + AS_FLOATS * 4u;
#pragma unroll
        for (int i = 0; i < 8; i++) {
            const int q = tid + i * 256;
            const int row = q >> 3, qq = q & 7;
            CP_ASYNC16(bu + (uint32_t)(row * ASTR + qq * 4) * 4u,
                       BT + (size_t)(n0 + row) * K + t * BK + qq * 4);
        }
    };

    issue(0);
    CP_COMMIT();

    for (int t = 0; t < T; t++) {
        if (t + 1 < T) {
            issue(t + 1);
            CP_COMMIT();
            CP_WAIT(1);
        } else {
            CP_WAIT(0);
        }
        __syncthreads();

        const float* As = stage0 + (t & 1) * STG_FLOATS;
        const float* Bs = As + AS_FLOATS;

#pragma unroll
        for (int kk = 0; kk < 4; kk++) {
            uint32_t af[4][4];
#pragma unroll
            for (int mt = 0; mt < 4; mt++) {
                const int mb = wr * 64 + mt * 16;
                af[mt][0] = *(const uint32_t*)&As[(mb + r) * ASTR + kk * 8 + c];
                af[mt][1] = *(const uint32_t*)&As[(mb + r + 8) * ASTR + kk * 8 + c];
                af[mt][2] = *(const uint32_t*)&As[(mb + r) * ASTR + kk * 8 + c + 4];
                af[mt][3] = *(const uint32_t*)&As[(mb + r + 8) * ASTR + kk * 8 + c + 4];
            }
            uint32_t bf[8][2];
#pragma unroll
            for (int nt = 0; nt < 8; nt++) {
                const int bn = wc * 64 + nt * 8 + r;
                bf[nt][0] = *(const uint32_t*)&Bs[bn * ASTR + kk * 8 + c];
                bf[nt][1] = *(const uint32_t*)&Bs[bn * ASTR + kk * 8 + c + 4];
            }
#pragma unroll
            for (int mt = 0; mt < 4; mt++)
#pragma unroll
                for (int nt = 0; nt < 8; nt++)
                    mma_tf32(acc[mt][nt][0], acc[mt][nt][1],
                             acc[mt][nt][2], acc[mt][nt][3],
                             af[mt][0], af[mt][1], af[mt][2], af[mt][3],
                             bf[nt][0], bf[nt][1]);
        }
        __syncthreads();
    }

#pragma unroll
    for (int mt = 0; mt < 4; mt++) {
        const int row0 = m0 + wr * 64 + mt * 16 + r;
#pragma unroll
        for (int nt = 0; nt < 8; nt++) {
            const int col = n0 + wc * 64 + nt * 8 + c * 2;
            const float bx = bias_s[wc * 64 + nt * 8 + c * 2];
            const float by = bias_s[wc * 64 + nt * 8 + c * 2 + 1];
            float v0 = acc[mt][nt][0] + bx;
            float v1 = acc[mt][nt][1] + by;
            float v2 = acc[mt][nt][2] + bx;
            float v3 = acc[mt][nt][3] + by;
            if (relu) {
                v0 = fmaxf(v0, 0.f); v1 = fmaxf(v1, 0.f);
                v2 = fmaxf(v2, 0.f); v3 = fmaxf(v3, 0.f);
            }
            if (roundout) {
                v0 = to_tf32(v0); v1 = to_tf32(v1);
                v2 = to_tf32(v2); v3 = to_tf32(v3);
            }
            *(float2*)&C[(size_t)row0 * Ntot + col] = make_float2(v0, v1);
            *(float2*)&C[(size_t)(row0 + 8) * Ntot + col] = make_float2(v2, v3);
        }
    }
}

// ---------------------------------------------------------------------------
// prep kernels
// ---------------------------------------------------------------------------
__global__ void __launch_bounds__(256) cvt_x(
    const float* __restrict__ in, float* __restrict__ outp, int n4)
{
    const int i = blockIdx.x * 256 + threadIdx.x;
    if (i < n4) {
        float4 v = ((const float4*)in)[i];
        v.x = to_tf32(v.x); v.y = to_tf32(v.y);
        v.z = to_tf32(v.z); v.w = to_tf32(v.w);
        ((float4*)outp)[i] = v;
    }
}

__global__ void __launch_bounds__(256) transpose_cvt(
    const float* __restrict__ W, float* __restrict__ WT, int K, int N)
{
    __shared__ float t[32][33];
    const int bx = blockIdx.x * 32;
    const int by = blockIdx.y * 32;
    const int x = threadIdx.x & 31;
    const int y = threadIdx.x >> 5;
#pragma unroll
    for (int i = 0; i < 32; i += 8)
        t[y + i][x] = to_tf32(W[(size_t)(by + y + i) * N + bx + x]);
    __syncthreads();
#pragma unroll
    for (int i = 0; i < 32; i += 8)
        WT[(size_t)(bx + y + i) * K + by + x] = t[x][y + i];
}

// Transpose per-feature uni weights: uw2[i][fi][fo] -> uw2t[i][fo][fi] (tf32),
// uw3[i][fi][fo] -> uw3t[i][fo][fi] (tf32). One block per feature.
__global__ void __launch_bounds__(256) uni_w_prep(
    const float* __restrict__ uw2, const float* __restrict__ uw3,
    float* __restrict__ uw2t, float* __restrict__ uw3t)
{
    __shared__ float t2[32][33];
    __shared__ float t3[32][17];
    const int i = blockIdx.x;
    const int tid = threadIdx.x;

    {   // load uw2[i]: 1024 floats, tid*4 each
        float4 v = ((const float4*)(uw2 + (size_t)i * UH * UH))[tid];
        const int fi = tid >> 3;
        const int fo = (tid & 7) * 4;
        t2[fi][fo + 0] = to_tf32(v.x);
        t2[fi][fo + 1] = to_tf32(v.y);
        t2[fi][fo + 2] = to_tf32(v.z);
        t2[fi][fo + 3] = to_tf32(v.w);
    }
    {   // load uw3[i]: 512 floats, tid*2 each
        float2 v = ((const float2*)(uw3 + (size_t)i * UH * NOUT))[tid];
        const int fi = tid >> 3;
        const int fo = (tid & 7) * 2;
        t3[fi][fo + 0] = to_tf32(v.x);
        t3[fi][fo + 1] = to_tf32(v.y);
    }
    __syncthreads();
    {   // store uw2t[i][fo][fi]
        const int fo = tid >> 3;
        const int fi = (tid & 7) * 4;
        float4 o;
        o.x = t2[fi + 0][fo]; o.y = t2[fi + 1][fo];
        o.z = t2[fi + 2][fo]; o.w = t2[fi + 3][fo];
        ((float4*)(uw2t + (size_t)i * UH * UH))[tid] = o;
    }
    {   // store uw3t[i][fo][fi]
        const int fo = tid >> 4;
        const int fi = (tid & 15) * 2;
        float2 o;
        o.x = t3[fi + 0][fo]; o.y = t3[fi + 1][fo];
        ((float2*)(uw3t + (size_t)i * NOUT * UH))[tid] = o;
    }
}

// ---------------------------------------------------------------------------
// Output layer (unchanged)
// ---------------------------------------------------------------------------
__global__ void __launch_bounds__(256) gemm_out(
    const float* __restrict__ Hin, const float* __restrict__ W2,
    const float* __restrict__ b2, float* __restrict__ out)
{
    const int idx = blockIdx.x * 256 + threadIdx.x;
    const int b = idx >> 2;
    const int og = (idx & 3) * 4;
    const float* h = Hin + (size_t)b * HID;
    float4 acc = *(const float4*)(b2 + og);
#pragma unroll 4
    for (int k = 0; k < HID; k++) {
        const float hv = h[k];
        const float4 w = *(const float4*)(W2 + k * NOUT + og);
        acc.x = fmaf(hv, w.x, acc.x);
        acc.y = fmaf(hv, w.y, acc.y);
        acc.z = fmaf(hv, w.z, acc.z);
        acc.w = fmaf(hv, w.w, acc.w);
    }
    *(float4*)(out + (size_t)b * NOUT + og) = acc;
}

// ---------------------------------------------------------------------------
// Tensor-core uni MLPs.
// CTA = 128 batch rows x 128 features (grid 128 x 2), 256 threads, 8 warps.
// Warp w owns rows 16w..16w+15: h1 compute, mma2, h2, mma3 are all warp-local
// (__syncwarp only); __syncthreads only brackets cp.async weight staging.
// ---------------------------------------------------------------------------
#define USTR 36
#define H1_OFF 0
#define H2_OFF (128 * USTR)                 // 4608
#define WBUF0  (2 * 128 * USTR)             // 9216
#define WBUF_FLOATS 1840
// within wbuf (floats): w2t=0 (32x36), w3t=1152 (16x36), w1=1728, b1=1760,
//                       b2=1792, b3=1824
#define UNI_SMEM ((WBUF0 + 2 * WBUF_FLOATS) * 4)   // 51584 B
#define NF 128

__global__ void __launch_bounds__(256, 2) uni_tc(
    const float* __restrict__ x,
    const float* __restrict__ uw1, const float* __restrict__ ub1,
    const float* __restrict__ uw2t, const float* __restrict__ ub2,
    const float* __restrict__ uw3t, const float* __restrict__ ub3,
    float* __restrict__ out)
{
    extern __shared__ float sm[];
    const uint32_t smu = smem_u32(sm);

    const int tid = threadIdx.x;
    const int lane = tid & 31;
    const int w = tid >> 5;
    const int r = lane >> 2;
    const int c = lane & 3;
    const int i0 = blockIdx.y * NF;
    const int row_l = tid >> 1;                       // 0..127, warp-local
    const int row_g = blockIdx.x * 128 + row_l;

    // cp.async staging of one feature's weights (412 x 16B chunks)
    auto stage = [&](int j, int buf) {
        const int i = i0 + j;
        const uint32_t wb = smu + (uint32_t)(WBUF0 + buf * WBUF_FLOATS) * 4u;
#pragma unroll
        for (int cb = 0; cb < 2; cb++) {
            const int ch = tid + cb * 256;
            if (ch < 412) {
                uint32_t dst; const float* src;
                if (ch < 256) {
                    const int fo = ch >> 3, p = ch & 7;
                    dst = wb + fo * 144 + p * 16;
                    src = uw2t + (size_t)i * 1024 + fo * 32 + p * 4;
                } else if (ch < 384) {
                    const int c2 = ch - 256, fo = c2 >> 3, p = c2 & 7;
                    dst = wb + 4608 + fo * 144 + p * 16;
                    src = uw3t + (size_t)i * 512 + fo * 32 + p * 4;
                } else if (ch < 392) {
                    const int p = ch - 384;
                    dst = wb + 6912 + p * 16;
                    src = uw1 + (size_t)i * 32 + p * 4;
                } else if (ch < 400) {
                    const int p = ch - 392;
                    dst = wb + 7040 + p * 16;
                    src = ub1 + (size_t)i * 32 + p * 4;
                } else if (ch < 408) {
                    const int p = ch - 400;
                    dst = wb + 7168 + p * 16;
                    src = ub2 + (size_t)i * 32 + p * 4;
                } else {
                    const int p = ch - 408;
                    dst = wb + 7296 + p * 16;
                    src = ub3 + (size_t)i * 16 + p * 4;
                }
                CP_ASYNC16(dst, src);
            }
        }
    };

    stage(0, 0); CP_COMMIT();
    stage(1, 1); CP_COMMIT();

    float xv = x[(size_t)row_g * NINP + i0];

    float uacc[2][4];
#pragma unroll
    for (int nt = 0; nt < 2; nt++)
#pragma unroll
        for (int j = 0; j < 4; j++) uacc[nt][j] = 0.f;

    float* h1w = sm + H1_OFF + (16 * w) * USTR;
    float* h2w = sm + H2_OFF + (16 * w) * USTR;

    for (int j = 0; j < NF; j++) {
        const int buf = j & 1;
        CP_WAIT(1);
        __syncthreads();

        const float* wb  = sm + WBUF0 + buf * WBUF_FLOATS;
        const float* w2t = wb;
        const float* w3t = wb + 1152;
        const float* w1s = wb + 1728;
        const float* b1s = wb + 1760;
        const float* b2s = wb + 1792;
        const float* b3s = wb + 1824;

        // ---- layer 1 (fp32 FFMA, tf32-rounded, vectorized smem stores) ----
        {
            const int f0 = (tid & 1) * 16;
            float* h1p = sm + H1_OFF + row_l * USTR + f0;
#pragma unroll
            for (int q4 = 0; q4 < 4; q4++) {
                float4 v;
                v.x = to_tf32(fmaxf(fmaf(xv, w1s[f0 + q4 * 4 + 0], b1s[f0 + q4 * 4 + 0]), 0.f));
                v.y = to_tf32(fmaxf(fmaf(xv, w1s[f0 + q4 * 4 + 1], b1s[f0 + q4 * 4 + 1]), 0.f));
                v.z = to_tf32(fmaxf(fmaf(xv, w1s[f0 + q4 * 4 + 2], b1s[f0 + q4 * 4 + 2]), 0.f));
                v.w = to_tf32(fmaxf(fmaf(xv, w1s[f0 + q4 * 4 + 3], b1s[f0 + q4 * 4 + 3]), 0.f));
                *(float4*)(h1p + q4 * 4) = v;
            }
        }
        if (j + 1 < NF) xv = x[(size_t)row_g * NINP + i0 + j + 1];
        __syncwarp(0xffffffffu);

        // ---- layer 2: h2 = relu(h1 @ w2 + b2), warp-local mma ----
        float c2[4][4];
#pragma unroll
        for (int nt = 0; nt < 4; nt++)
#pragma unroll
            for (int q = 0; q < 4; q++) c2[nt][q] = 0.f;
#pragma unroll
        for (int kk = 0; kk < 4; kk++) {
            uint32_t a0 = *(const uint32_t*)&h1w[r * USTR + kk * 8 + c];
            uint32_t a1 = *(const uint32_t*)&h1w[(r + 8) * USTR + kk * 8 + c];
            uint32_t a2 = *(const uint32_t*)&h1w[r * USTR + kk * 8 + c + 4];
            uint32_t a3 = *(const uint32_t*)&h1w[(r + 8) * USTR + kk * 8 + c + 4];
#pragma unroll
            for (int nt = 0; nt < 4; nt++) {
                uint32_t b0 = *(const uint32_t*)&w2t[(nt * 8 + r) * USTR + kk * 8 + c];
                uint32_t b1 = *(const uint32_t*)&w2t[(nt * 8 + r) * USTR + kk * 8 + c + 4];
                mma_tf32(c2[nt][0], c2[nt][1], c2[nt][2], c2[nt][3],
                         a0, a1, a2, a3, b0, b1);
            }
        }
#pragma unroll
        for (int nt = 0; nt < 4; nt++) {
            const int col = nt * 8 + 2 * c;
            const float bx = b2s[col], by = b2s[col + 1];
            float v0 = to_tf32(fmaxf(c2[nt][0] + bx, 0.f));
            float v1 = to_tf32(fmaxf(c2[nt][1] + by, 0.f));
            float v2 = to_tf32(fmaxf(c2[nt][2] + bx, 0.f));
            float v3 = to_tf32(fmaxf(c2[nt][3] + by, 0.f));
            *(float2*)&h2w[r * USTR + col] = make_float2(v0, v1);
            *(float2*)&h2w[(r + 8) * USTR + col] = make_float2(v2, v3);
        }
        __syncwarp(0xffffffffu);

        // ---- layer 3: acc += h2 @ w3 (+ b3), warp-local mma ----
#pragma unroll
        for (int kk = 0; kk < 4; kk++) {
            uint32_t a0 = *(const uint32_t*)&h2w[r * USTR + kk * 8 + c];
            uint32_t a1 = *(const uint32_t*)&h2w[(r + 8) * USTR + kk * 8 + c];
            uint32_t a2 = *(const uint32_t*)&h2w[r * USTR + kk * 8 + c + 4];
            uint32_t a3 = *(const uint32_t*)&h2w[(r + 8) * USTR + kk * 8 + c + 4];
#pragma unroll
            for (int nt = 0; nt < 2; nt++) {
                uint32_t b0 = *(const uint32_t*)&w3t[(nt * 8 + r) * USTR + kk * 8 + c];
                uint32_t b1 = *(const uint32_t*)&w3t[(nt * 8 + r) * USTR + kk * 8 + c + 4];
                mma_tf32(uacc[nt][0], uacc[nt][1], uacc[nt][2], uacc[nt][3],
                         a0, a1, a2, a3, b0, b1);
            }
        }
#pragma unroll
        for (int nt = 0; nt < 2; nt++) {
            const int col = nt * 8 + 2 * c;
            uacc[nt][0] += b3s[col];
            uacc[nt][1] += b3s[col + 1];
            uacc[nt][2] += b3s[col];
            uacc[nt][3] += b3s[col + 1];
        }

        __syncthreads();          // all warps done with wbuf before restage
        if (j + 2 < NF) stage(j + 2, buf);
        CP_COMMIT();
    }

    // ---- merge into out ----
    const int gr = blockIdx.x * 128 + 16 * w + r;
#pragma unroll
    for (int nt = 0; nt < 2; nt++) {
        const int col = nt * 8 + 2 * c;
        atomicAdd(&out[(size_t)gr * NOUT + col],       uacc[nt][0]);
        atomicAdd(&out[(size_t)gr * NOUT + col + 1],   uacc[nt][1]);
        atomicAdd(&out[(size_t)(gr + 8) * NOUT + col],     uacc[nt][2]);
        atomicAdd(&out[(size_t)(gr + 8) * NOUT + col + 1], uacc[nt][3]);
    }
}

// ---------------------------------------------------------------------------
extern "C" void kernel_launch(void* const* d_in, const int* in_sizes, int n_in,
                              void* d_out, int out_size)
{
    const float* x   = (const float*)d_in[0];
    const float* W0  = (const float*)d_in[1];
    const float* b0  = (const float*)d_in[2];
    const float* W1  = (const float*)d_in[3];
    const float* b1  = (const float*)d_in[4];
    const float* W2  = (const float*)d_in[5];
    const float* b2  = (const float*)d_in[6];
    const float* uw1 = (const float*)d_in[7];
    const float* ub1 = (const float*)d_in[8];
    const float* uw2 = (const float*)d_in[9];
    const float* ub2 = (const float*)d_in[10];
    const float* uw3 = (const float*)d_in[11];
    const float* ub3 = (const float*)d_in[12];
    float* out = (float*)d_out;

    float *h0, *h1, *xr, *w0t, *w1t, *uw2t, *uw3t;
    cudaGetSymbolAddress((void**)&h0, g_h0);
    cudaGetSymbolAddress((void**)&h1, g_h1);
    cudaGetSymbolAddress((void**)&xr, g_x);
    cudaGetSymbolAddress((void**)&w0t, g_w0t);
    cudaGetSymbolAddress((void**)&w1t, g_w1t);
    cudaGetSymbolAddress((void**)&uw2t, g_uw2t);
    cudaGetSymbolAddress((void**)&uw3t, g_uw3t);

    cudaFuncSetAttribute(mma_gemm, cudaFuncAttributeMaxDynamicSharedMemorySize, GEMM_SMEM);
    cudaFuncSetAttribute(uni_tc, cudaFuncAttributeMaxDynamicSharedMemorySize, UNI_SMEM);

    // prep: round x, transpose+round weights (main + uni)
    cvt_x<<<(BATCH * NINP / 4 + 255) / 256, 256>>>(x, xr, BATCH * NINP / 4);
    {
        dim3 g0(HID / 32, NINP / 32);
        transpose_cvt<<<g0, 256>>>(W0, w0t, NINP, HID);
        dim3 g1(HID / 32, HID / 32);
        transpose_cvt<<<g1, 256>>>(W1, w1t, HID, HID);
    }
    uni_w_prep<<<NINP, 256>>>(uw2, uw3, uw2t, uw3t);

    // main MLP
    {
        dim3 grid(HID / BN, BATCH / BM);
        mma_gemm<<<grid, 256, GEMM_SMEM>>>(xr, w0t, b0, h0, NINP, HID, 1, 1);
        mma_gemm<<<grid, 256, GEMM_SMEM>>>(h0, w1t, b1, h1, HID, HID, 1, 0);
    }
    gemm_out<<<(BATCH * 4) / 256, 256>>>(h1, W2, b2, out);

    // uni MLPs accumulate on top of out (tensor-core path)
    {
        dim3 grid(BATCH / 128, NINP / NF);
        uni_tc<<<grid, 256, UNI_SMEM>>>(x, uw1, ub1, uw2t, ub2, uw3t, ub3, out);
    }
}

// round 10
// speedup vs baseline: 2.2618x; 1.0009x over previous
#include <cuda_runtime.h>
#include <cstdint>

#define BATCH 16384
#define NINP  256
#define HID   1024
#define NOUT  16
#define UH    32

// ---------------------------------------------------------------------------
// Device scratch (no runtime allocation allowed)
// ---------------------------------------------------------------------------
__device__ float g_h0[BATCH * HID];
__device__ float g_h1[BATCH * HID];
__device__ float g_x[BATCH * NINP];    // x pre-rounded to tf32 (main GEMM A)
__device__ float g_w0t[HID * NINP];    // W0^T [HID][NINP], tf32-rounded
__device__ float g_w1t[HID * HID];     // W1^T, tf32-rounded
__device__ float g_uw2t[NINP * UH * UH];    // per-feature w2^T [i][fo][fi], tf32
__device__ float g_uw3t[NINP * UH * NOUT];  // per-feature w3^T [i][fo][fi], tf32
__device__ float g_uni[2 * BATCH * NOUT];   // uni partial sums, one slice/chunk

// ---------------------------------------------------------------------------
// Helpers
// ---------------------------------------------------------------------------
__device__ __forceinline__ uint32_t smem_u32(const void* p) {
    uint32_t a;
    asm("{ .reg .u64 t; cvta.to.shared.u64 t, %1; cvt.u32.u64 %0, t; }"
        : "=r"(a) : "l"(p));
    return a;
}

// tf32 destination is a .b32 register (storage format), per PTX ISA.
__device__ __forceinline__ float to_tf32(float x) {
    uint32_t r;
    asm("cvt.rna.tf32.f32 %0, %1;" : "=r"(r) : "f"(x));
    return __uint_as_float(r);
}

#define CP_ASYNC16(dst_u32, src_ptr) \
    asm volatile("cp.async.cg.shared.global [%0], [%1], 16;" \
        :: "r"(dst_u32), "l"(src_ptr))
#define CP_COMMIT() asm volatile("cp.async.commit_group;")
#define CP_WAIT(n)  asm volatile("cp.async.wait_group %0;" :: "n"(n))

__device__ __forceinline__ void mma_tf32(
    float& d0, float& d1, float& d2, float& d3,
    uint32_t a0, uint32_t a1, uint32_t a2, uint32_t a3,
    uint32_t b0, uint32_t b1)
{
    asm volatile(
        "mma.sync.aligned.m16n8k8.row.col.f32.tf32.tf32.f32 "
        "{%0,%1,%2,%3}, {%4,%5,%6,%7}, {%8,%9}, {%0,%1,%2,%3};"
        : "+f"(d0), "+f"(d1), "+f"(d2), "+f"(d3)
        : "r"(a0), "r"(a1), "r"(a2), "r"(a3), "r"(b0), "r"(b1));
}

// ---------------------------------------------------------------------------
// tf32 mma.sync GEMM (unchanged — measured 78us on GEMM1)
// ---------------------------------------------------------------------------
#define BM 128
#define BN 256
#define BK 32
#define ASTR 36
#define AS_FLOATS (BM * ASTR)
#define BS_FLOATS (BN * ASTR)
#define STG_FLOATS (AS_FLOATS + BS_FLOATS)
#define GEMM_SMEM ((BN + 2 * STG_FLOATS) * 4)

__global__ void __launch_bounds__(256, 1) mma_gemm(
    const float* __restrict__ A, const float* __restrict__ BT,
    const float* __restrict__ bias, float* __restrict__ C,
    int K, int Ntot, int relu, int roundout)
{
    extern __shared__ float sm[];
    float* bias_s = sm;
    float* stage0 = sm + BN;
    const uint32_t stage0_u32 = smem_u32(stage0);

    const int tid = threadIdx.x;
    const int lane = tid & 31;
    const int wid = tid >> 5;
    const int wr = wid >> 2;
    const int wc = wid & 3;
    const int m0 = blockIdx.y * BM;
    const int n0 = blockIdx.x * BN;

    if (tid < BN) bias_s[tid] = bias[n0 + tid];

    const int r = lane >> 2;
    const int c = lane & 3;

    float acc[4][8][4];
#pragma unroll
    for (int mt = 0; mt < 4; mt++)
#pragma unroll
        for (int nt = 0; nt < 8; nt++)
#pragma unroll
            for (int j = 0; j < 4; j++) acc[mt][nt][j] = 0.f;

    const int T = K / BK;

    auto issue = [&](int t) {
        const uint32_t su = stage0_u32 + (uint32_t)((t & 1) * STG_FLOATS) * 4u;
#pragma unroll
        for (int i = 0; i < 4; i++) {
            const int q = tid + i * 256;
            const int row = q >> 3, qq = q & 7;
            CP_ASYNC16(su + (uint32_t)(row * ASTR + qq * 4) * 4u,
                       A + (size_t)(m0 + row) * K + t * BK + qq * 4);
        }
        const uint32_t bu = su + AS_FLOATS * 4u;
#pragma unroll
        for (int i = 0; i < 8; i++) {
            const int q = tid + i * 256;
            const int row = q >> 3, qq = q & 7;
            CP_ASYNC16(bu + (uint32_t)(row * ASTR + qq * 4) * 4u,
                       BT + (size_t)(n0 + row) * K + t * BK + qq * 4);
        }
    };

    issue(0);
    CP_COMMIT();

    for (int t = 0; t < T; t++) {
        if (t + 1 < T) {
            issue(t + 1);
            CP_COMMIT();
            CP_WAIT(1);
        } else {
            CP_WAIT(0);
        }
        __syncthreads();

        const float* As = stage0 + (t & 1) * STG_FLOATS;
        const float* Bs = As + AS_FLOATS;

#pragma unroll
        for (int kk = 0; kk < 4; kk++) {
            uint32_t af[4][4];
#pragma unroll
            for (int mt = 0; mt < 4; mt++) {
                const int mb = wr * 64 + mt * 16;
                af[mt][0] = *(const uint32_t*)&As[(mb + r) * ASTR + kk * 8 + c];
                af[mt][1] = *(const uint32_t*)&As[(mb + r + 8) * ASTR + kk * 8 + c];
                af[mt][2] = *(const uint32_t*)&As[(mb + r) * ASTR + kk * 8 + c + 4];
                af[mt][3] = *(const uint32_t*)&As[(mb + r + 8) * ASTR + kk * 8 + c + 4];
            }
            uint32_t bf[8][2];
#pragma unroll
            for (int nt = 0; nt < 8; nt++) {
                const int bn = wc * 64 + nt * 8 + r;
                bf[nt][0] = *(const uint32_t*)&Bs[bn * ASTR + kk * 8 + c];
                bf[nt][1] = *(const uint32_t*)&Bs[bn * ASTR + kk * 8 + c + 4];
            }
#pragma unroll
            for (int mt = 0; mt < 4; mt++)
#pragma unroll
                for (int nt = 0; nt < 8; nt++)
                    mma_tf32(acc[mt][nt][0], acc[mt][nt][1],
                             acc[mt][nt][2], acc[mt][nt][3],
                             af[mt][0], af[mt][1], af[mt][2], af[mt][3],
                             bf[nt][0], bf[nt][1]);
        }
        __syncthreads();
    }

#pragma unroll
    for (int mt = 0; mt < 4; mt++) {
        const int row0 = m0 + wr * 64 + mt * 16 + r;
#pragma unroll
        for (int nt = 0; nt < 8; nt++) {
            const int col = n0 + wc * 64 + nt * 8 + c * 2;
            const float bx = bias_s[wc * 64 + nt * 8 + c * 2];
            const float by = bias_s[wc * 64 + nt * 8 + c * 2 + 1];
            float v0 = acc[mt][nt][0] + bx;
            float v1 = acc[mt][nt][1] + by;
            float v2 = acc[mt][nt][2] + bx;
            float v3 = acc[mt][nt][3] + by;
            if (relu) {
                v0 = fmaxf(v0, 0.f); v1 = fmaxf(v1, 0.f);
                v2 = fmaxf(v2, 0.f); v3 = fmaxf(v3, 0.f);
            }
            if (roundout) {
                v0 = to_tf32(v0); v1 = to_tf32(v1);
                v2 = to_tf32(v2); v3 = to_tf32(v3);
            }
            *(float2*)&C[(size_t)row0 * Ntot + col] = make_float2(v0, v1);
            *(float2*)&C[(size_t)(row0 + 8) * Ntot + col] = make_float2(v2, v3);
        }
    }
}

// ---------------------------------------------------------------------------
// prep kernels
// ---------------------------------------------------------------------------
__global__ void __launch_bounds__(256) cvt_x(
    const float* __restrict__ in, float* __restrict__ outp, int n4)
{
    const int i = blockIdx.x * 256 + threadIdx.x;
    if (i < n4) {
        float4 v = ((const float4*)in)[i];
        v.x = to_tf32(v.x); v.y = to_tf32(v.y);
        v.z = to_tf32(v.z); v.w = to_tf32(v.w);
        ((float4*)outp)[i] = v;
    }
}

__global__ void __launch_bounds__(256) transpose_cvt(
    const float* __restrict__ W, float* __restrict__ WT, int K, int N)
{
    __shared__ float t[32][33];
    const int bx = blockIdx.x * 32;
    const int by = blockIdx.y * 32;
    const int x = threadIdx.x & 31;
    const int y = threadIdx.x >> 5;
#pragma unroll
    for (int i = 0; i < 32; i += 8)
        t[y + i][x] = to_tf32(W[(size_t)(by + y + i) * N + bx + x]);
    __syncthreads();
#pragma unroll
    for (int i = 0; i < 32; i += 8)
        WT[(size_t)(bx + y + i) * K + by + x] = t[x][y + i];
}

// Transpose per-feature uni weights to [i][fo][fi], tf32-rounded.
__global__ void __launch_bounds__(256) uni_w_prep(
    const float* __restrict__ uw2, const float* __restrict__ uw3,
    float* __restrict__ uw2t, float* __restrict__ uw3t)
{
    __shared__ float t2[32][33];
    __shared__ float t3[32][17];
    const int i = blockIdx.x;
    const int tid = threadIdx.x;

    {
        float4 v = ((const float4*)(uw2 + (size_t)i * UH * UH))[tid];
        const int fi = tid >> 3;
        const int fo = (tid & 7) * 4;
        t2[fi][fo + 0] = to_tf32(v.x);
        t2[fi][fo + 1] = to_tf32(v.y);
        t2[fi][fo + 2] = to_tf32(v.z);
        t2[fi][fo + 3] = to_tf32(v.w);
    }
    {
        float2 v = ((const float2*)(uw3 + (size_t)i * UH * NOUT))[tid];
        const int fi = tid >> 3;
        const int fo = (tid & 7) * 2;
        t3[fi][fo + 0] = to_tf32(v.x);
        t3[fi][fo + 1] = to_tf32(v.y);
    }
    __syncthreads();
    {
        const int fo = tid >> 3;
        const int fi = (tid & 7) * 4;
        float4 o;
        o.x = t2[fi + 0][fo]; o.y = t2[fi + 1][fo];
        o.z = t2[fi + 2][fo]; o.w = t2[fi + 3][fo];
        ((float4*)(uw2t + (size_t)i * UH * UH))[tid] = o;
    }
    {
        const int fo = tid >> 4;
        const int fi = (tid & 15) * 2;
        float2 o;
        o.x = t3[fi + 0][fo]; o.y = t3[fi + 1][fo];
        ((float2*)(uw3t + (size_t)i * NOUT * UH))[tid] = o;
    }
}

// ---------------------------------------------------------------------------
// Output layer: out = h1 @ W2 + b2 + uni0 + uni1  (fuses uni merge; no atomics)
// ---------------------------------------------------------------------------
__global__ void __launch_bounds__(256) gemm_out(
    const float* __restrict__ Hin, const float* __restrict__ W2,
    const float* __restrict__ b2, const float* __restrict__ uni,
    float* __restrict__ out)
{
    const int idx = blockIdx.x * 256 + threadIdx.x;
    const int b = idx >> 2;
    const int og = (idx & 3) * 4;
    const float* h = Hin + (size_t)b * HID;
    float4 acc = *(const float4*)(b2 + og);
    {
        const float4 u0 = *(const float4*)(uni + (size_t)b * NOUT + og);
        const float4 u1 = *(const float4*)(uni + (size_t)(BATCH + b) * NOUT + og);
        acc.x += u0.x + u1.x;
        acc.y += u0.y + u1.y;
        acc.z += u0.z + u1.z;
        acc.w += u0.w + u1.w;
    }
#pragma unroll 4
    for (int k = 0; k < HID; k++) {
        const float hv = h[k];
        const float4 w = *(const float4*)(W2 + k * NOUT + og);
        acc.x = fmaf(hv, w.x, acc.x);
        acc.y = fmaf(hv, w.y, acc.y);
        acc.z = fmaf(hv, w.z, acc.z);
        acc.w = fmaf(hv, w.w, acc.w);
    }
    *(float4*)(out + (size_t)b * NOUT + og) = acc;
}

// ---------------------------------------------------------------------------
// Tensor-core uni MLPs (R7-proven structure).
// CTA = 128 batch rows x 128 features (grid 128 x 2), 256 threads, 8 warps.
// Each chunk writes its own g_uni slice with plain stores (no atomics).
// ---------------------------------------------------------------------------
#define USTR 36
#define H1_OFF 0
#define H2_OFF (128 * USTR)                 // 4608
#define WBUF0  (2 * 128 * USTR)             // 9216
#define WBUF_FLOATS 1840
// wbuf layout (floats): w2t=0 (32x36), w3t=1152 (16x36), w1=1728, b1=1760,
//                       b2=1792, b3=1824
#define UNI_SMEM ((WBUF0 + 2 * WBUF_FLOATS) * 4)   // 51584 B
#define NF 128

__global__ void __launch_bounds__(256, 2) uni_tc(
    const float* __restrict__ x,
    const float* __restrict__ uw1, const float* __restrict__ ub1,
    const float* __restrict__ uw2t, const float* __restrict__ ub2,
    const float* __restrict__ uw3t, const float* __restrict__ ub3,
    float* __restrict__ uni_out)
{
    extern __shared__ float sm[];
    const uint32_t smu = smem_u32(sm);

    const int tid = threadIdx.x;
    const int lane = tid & 31;
    const int w = tid >> 5;
    const int r = lane >> 2;
    const int c = lane & 3;
    const int i0 = blockIdx.y * NF;
    const int row_l = tid >> 1;                       // 0..127, warp-local
    const int row_g = blockIdx.x * 128 + row_l;

    // cp.async staging of one feature's weights (412 x 16B chunks)
    auto stage = [&](int j, int buf) {
        const int i = i0 + j;
        const uint32_t wb = smu + (uint32_t)(WBUF0 + buf * WBUF_FLOATS) * 4u;
#pragma unroll
        for (int cb = 0; cb < 2; cb++) {
            const int ch = tid + cb * 256;
            if (ch < 412) {
                uint32_t dst; const float* src;
                if (ch < 256) {
                    const int fo = ch >> 3, p = ch & 7;
                    dst = wb + fo * 144 + p * 16;
                    src = uw2t + (size_t)i * 1024 + fo * 32 + p * 4;
                } else if (ch < 384) {
                    const int c2 = ch - 256, fo = c2 >> 3, p = c2 & 7;
                    dst = wb + 4608 + fo * 144 + p * 16;
                    src = uw3t + (size_t)i * 512 + fo * 32 + p * 4;
                } else if (ch < 392) {
                    const int p = ch - 384;
                    dst = wb + 6912 + p * 16;
                    src = uw1 + (size_t)i * 32 + p * 4;
                } else if (ch < 400) {
                    const int p = ch - 392;
                    dst = wb + 7040 + p * 16;
                    src = ub1 + (size_t)i * 32 + p * 4;
                } else if (ch < 408) {
                    const int p = ch - 400;
                    dst = wb + 7168 + p * 16;
                    src = ub2 + (size_t)i * 32 + p * 4;
                } else {
                    const int p = ch - 408;
                    dst = wb + 7296 + p * 16;
                    src = ub3 + (size_t)i * 16 + p * 4;
                }
                CP_ASYNC16(dst, src);
            }
        }
    };

    stage(0, 0); CP_COMMIT();
    stage(1, 1); CP_COMMIT();

    float xv = x[(size_t)row_g * NINP + i0];

    float uacc[2][4];
#pragma unroll
    for (int nt = 0; nt < 2; nt++)
#pragma unroll
        for (int j = 0; j < 4; j++) uacc[nt][j] = 0.f;

    float* h1w = sm + H1_OFF + (16 * w) * USTR;
    float* h2w = sm + H2_OFF + (16 * w) * USTR;

    for (int j = 0; j < NF; j++) {
        const int buf = j & 1;
        CP_WAIT(1);
        __syncthreads();

        const float* wb  = sm + WBUF0 + buf * WBUF_FLOATS;
        const float* w2t = wb;
        const float* w3t = wb + 1152;
        const float* w1s = wb + 1728;
        const float* b1s = wb + 1760;
        const float* b2s = wb + 1792;
        const float* b3s = wb + 1824;

        // ---- layer 1 (fp32 FFMA, tf32-rounded, vectorized smem stores) ----
        {
            const int f0 = (tid & 1) * 16;
            float* h1p = sm + H1_OFF + row_l * USTR + f0;
#pragma unroll
            for (int q4 = 0; q4 < 4; q4++) {
                float4 v;
                v.x = to_tf32(fmaxf(fmaf(xv, w1s[f0 + q4 * 4 + 0], b1s[f0 + q4 * 4 + 0]), 0.f));
                v.y = to_tf32(fmaxf(fmaf(xv, w1s[f0 + q4 * 4 + 1], b1s[f0 + q4 * 4 + 1]), 0.f));
                v.z = to_tf32(fmaxf(fmaf(xv, w1s[f0 + q4 * 4 + 2], b1s[f0 + q4 * 4 + 2]), 0.f));
                v.w = to_tf32(fmaxf(fmaf(xv, w1s[f0 + q4 * 4 + 3], b1s[f0 + q4 * 4 + 3]), 0.f));
                *(float4*)(h1p + q4 * 4) = v;
            }
        }
        if (j + 1 < NF) xv = x[(size_t)row_g * NINP + i0 + j + 1];
        __syncwarp(0xffffffffu);

        // ---- layer 2: h2 = relu(h1 @ w2 + b2), warp-local mma ----
        float c2[4][4];
#pragma unroll
        for (int nt = 0; nt < 4; nt++)
#pragma unroll
            for (int q = 0; q < 4; q++) c2[nt][q] = 0.f;
#pragma unroll
        for (int kk = 0; kk < 4; kk++) {
            uint32_t a0 = *(const uint32_t*)&h1w[r * USTR + kk * 8 + c];
            uint32_t a1 = *(const uint32_t*)&h1w[(r + 8) * USTR + kk * 8 + c];
            uint32_t a2 = *(const uint32_t*)&h1w[r * USTR + kk * 8 + c + 4];
            uint32_t a3 = *(const uint32_t*)&h1w[(r + 8) * USTR + kk * 8 + c + 4];
#pragma unroll
            for (int nt = 0; nt < 4; nt++) {
                uint32_t b0 = *(const uint32_t*)&w2t[(nt * 8 + r) * USTR + kk * 8 + c];
                uint32_t b1 = *(const uint32_t*)&w2t[(nt * 8 + r) * USTR + kk * 8 + c + 4];
                mma_tf32(c2[nt][0], c2[nt][1], c2[nt][2], c2[nt][3],
                         a0, a1, a2, a3, b0, b1);
            }
        }
#pragma unroll
        for (int nt = 0; nt < 4; nt++) {
            const int col = nt * 8 + 2 * c;
            const float bx = b2s[col], by = b2s[col + 1];
            float v0 = to_tf32(fmaxf(c2[nt][0] + bx, 0.f));
            float v1 = to_tf32(fmaxf(c2[nt][1] + by, 0.f));
            float v2 = to_tf32(fmaxf(c2[nt][2] + bx, 0.f));
            float v3 = to_tf32(fmaxf(c2[nt][3] + by, 0.f));
            *(float2*)&h2w[r * USTR + col] = make_float2(v0, v1);
            *(float2*)&h2w[(r + 8) * USTR + col] = make_float2(v2, v3);
        }
        __syncwarp(0xffffffffu);

        // ---- layer 3: acc += h2 @ w3 (+ b3), warp-local mma ----
#pragma unroll
        for (int kk = 0; kk < 4; kk++) {
            uint32_t a0 = *(const uint32_t*)&h2w[r * USTR + kk * 8 + c];
            uint32_t a1 = *(const uint32_t*)&h2w[(r + 8) * USTR + kk * 8 + c];
            uint32_t a2 = *(const uint32_t*)&h2w[r * USTR + kk * 8 + c + 4];
            uint32_t a3 = *(const uint32_t*)&h2w[(r + 8) * USTR + kk * 8 + c + 4];
#pragma unroll
            for (int nt = 0; nt < 2; nt++) {
                uint32_t b0 = *(const uint32_t*)&w3t[(nt * 8 + r) * USTR + kk * 8 + c];
                uint32_t b1 = *(const uint32_t*)&w3t[(nt * 8 + r) * USTR + kk * 8 + c + 4];
                mma_tf32(uacc[nt][0], uacc[nt][1], uacc[nt][2], uacc[nt][3],
                         a0, a1, a2, a3, b0, b1);
            }
        }
#pragma unroll
        for (int nt = 0; nt < 2; nt++) {
            const int col = nt * 8 + 2 * c;
            uacc[nt][0] += b3s[col];
            uacc[nt][1] += b3s[col + 1];
            uacc[nt][2] += b3s[col];
            uacc[nt][3] += b3s[col + 1];
        }

        __syncthreads();          // all warps done with wbuf before restage
        if (j + 2 < NF) stage(j + 2, buf);
        CP_COMMIT();
    }

    // ---- write partial sums to this chunk's slice (plain stores) ----
    float* dst = uni_out + (size_t)blockIdx.y * BATCH * NOUT;
    const int gr = blockIdx.x * 128 + 16 * w + r;
#pragma unroll
    for (int nt = 0; nt < 2; nt++) {
        const int col = nt * 8 + 2 * c;
        *(float2*)&dst[(size_t)gr * NOUT + col] = make_float2(uacc[nt][0], uacc[nt][1]);
        *(float2*)&dst[(size_t)(gr + 8) * NOUT + col] = make_float2(uacc[nt][2], uacc[nt][3]);
    }
}

// ---------------------------------------------------------------------------
extern "C" void kernel_launch(void* const* d_in, const int* in_sizes, int n_in,
                              void* d_out, int out_size)
{
    const float* x   = (const float*)d_in[0];
    const float* W0  = (const float*)d_in[1];
    const float* b0  = (const float*)d_in[2];
    const float* W1  = (const float*)d_in[3];
    const float* b1  = (const float*)d_in[4];
    const float* W2  = (const float*)d_in[5];
    const float* b2  = (const float*)d_in[6];
    const float* uw1 = (const float*)d_in[7];
    const float* ub1 = (const float*)d_in[8];
    const float* uw2 = (const float*)d_in[9];
    const float* ub2 = (const float*)d_in[10];
    const float* uw3 = (const float*)d_in[11];
    const float* ub3 = (const float*)d_in[12];
    float* out = (float*)d_out;

    float *h0, *h1, *xr, *w0t, *w1t, *uw2t, *uw3t, *uni;
    cudaGetSymbolAddress((void**)&h0, g_h0);
    cudaGetSymbolAddress((void**)&h1, g_h1);
    cudaGetSymbolAddress((void**)&xr, g_x);
    cudaGetSymbolAddress((void**)&w0t, g_w0t);
    cudaGetSymbolAddress((void**)&w1t, g_w1t);
    cudaGetSymbolAddress((void**)&uw2t, g_uw2t);
    cudaGetSymbolAddress((void**)&uw3t, g_uw3t);
    cudaGetSymbolAddress((void**)&uni, g_uni);

    cudaFuncSetAttribute(mma_gemm, cudaFuncAttributeMaxDynamicSharedMemorySize, GEMM_SMEM);
    cudaFuncSetAttribute(uni_tc, cudaFuncAttributeMaxDynamicSharedMemorySize, UNI_SMEM);

    // prep
    cvt_x<<<(BATCH * NINP / 4 + 255) / 256, 256>>>(x, xr, BATCH * NINP / 4);
    {
        dim3 g0(HID / 32, NINP / 32);
        transpose_cvt<<<g0, 256>>>(W0, w0t, NINP, HID);
        dim3 g1(HID / 32, HID / 32);
        transpose_cvt<<<g1, 256>>>(W1, w1t, HID, HID);
    }
    uni_w_prep<<<NINP, 256>>>(uw2, uw3, uw2t, uw3t);

    // uni MLPs -> g_uni slices (independent of main MLP; launched early so the
    // ncu skip-window lands on it)
    {
        dim3 grid(BATCH / 128, 2);
        uni_tc<<<grid, 256, UNI_SMEM>>>(x, uw1, ub1, uw2t, ub2, uw3t, ub3, uni);
    }

    // main MLP
    {
        dim3 grid(HID / BN, BATCH / BM);
        mma_gemm<<<grid, 256, GEMM_SMEM>>>(xr, w0t, b0, h0, NINP, HID, 1, 1);
        mma_gemm<<<grid, 256, GEMM_SMEM>>>(h0, w1t, b1, h1, HID, HID, 1, 0);
    }

    // out = h1 @ W2 + b2 + uni0 + uni1
    gemm_out<<<(BATCH * 4) / 256, 256>>>(h1, W2, b2, uni, out);
}

// round 12
// speedup vs baseline: 2.3714x; 1.0485x over previous
#include <cuda_runtime.h>
#include <cstdint>

#define BATCH 16384
#define NINP  256
#define HID   1024
#define NOUT  16
#define UH    32

// ---------------------------------------------------------------------------
// Device scratch (no runtime allocation allowed)
// ---------------------------------------------------------------------------
__device__ float g_h0[BATCH * HID];
__device__ float g_h1[BATCH * HID];
__device__ float g_x[BATCH * NINP];    // x pre-rounded to tf32 (main GEMM A)
__device__ float g_xt[NINP * BATCH];   // x^T, tf32-rounded (uni layer-1 input)
__device__ float g_w0t[HID * NINP];    // W0^T [HID][NINP], tf32-rounded
__device__ float g_w1t[HID * HID];     // W1^T, tf32-rounded
__device__ float g_uw2t[NINP * UH * UH];    // per-feature w2^T [i][fo][fi], tf32
__device__ float g_uw3t[NINP * UH * NOUT];  // per-feature w3^T [i][fo][fi], tf32
__device__ float g_uni[BATCH * NOUT];       // uni sums (zeroed, atomic merge)

// ---------------------------------------------------------------------------
// Helpers
// ---------------------------------------------------------------------------
__device__ __forceinline__ uint32_t smem_u32(const void* p) {
    uint32_t a;
    asm("{ .reg .u64 t; cvta.to.shared.u64 t, %1; cvt.u32.u64 %0, t; }"
        : "=r"(a) : "l"(p));
    return a;
}

// tf32 destination is a .b32 register (storage format), per PTX ISA.
__device__ __forceinline__ float to_tf32(float x) {
    uint32_t r;
    asm("cvt.rna.tf32.f32 %0, %1;" : "=r"(r) : "f"(x));
    return __uint_as_float(r);
}
__device__ __forceinline__ uint32_t tf32_bits(float x) {
    uint32_t r;
    asm("cvt.rna.tf32.f32 %0, %1;" : "=r"(r) : "f"(x));
    return r;
}

#define CP_ASYNC16(dst_u32, src_ptr) \
    asm volatile("cp.async.cg.shared.global [%0], [%1], 16;" \
        :: "r"(dst_u32), "l"(src_ptr))
#define CP_COMMIT() asm volatile("cp.async.commit_group;")
#define CP_WAIT(n)  asm volatile("cp.async.wait_group %0;" :: "n"(n))

__device__ __forceinline__ void mma_tf32(
    float& d0, float& d1, float& d2, float& d3,
    uint32_t a0, uint32_t a1, uint32_t a2, uint32_t a3,
    uint32_t b0, uint32_t b1)
{
    asm volatile(
        "mma.sync.aligned.m16n8k8.row.col.f32.tf32.tf32.f32 "
        "{%0,%1,%2,%3}, {%4,%5,%6,%7}, {%8,%9}, {%0,%1,%2,%3};"
        : "+f"(d0), "+f"(d1), "+f"(d2), "+f"(d3)
        : "r"(a0), "r"(a1), "r"(a2), "r"(a3), "r"(b0), "r"(b1));
}

// ---------------------------------------------------------------------------
// tf32 mma.sync GEMM (unchanged — measured 78us on GEMM1)
// ---------------------------------------------------------------------------
#define BM 128
#define BN 256
#define BK 32
#define ASTR 36
#define AS_FLOATS (BM * ASTR)
#define BS_FLOATS (BN * ASTR)
#define STG_FLOATS (AS_FLOATS + BS_FLOATS)
#define GEMM_SMEM ((BN + 2 * STG_FLOATS) * 4)

__global__ void __launch_bounds__(256, 1) mma_gemm(
    const float* __restrict__ A, const float* __restrict__ BT,
    const float* __restrict__ bias, float* __restrict__ C,
    int K, int Ntot, int relu, int roundout)
{
    extern __shared__ float sm[];
    float* bias_s = sm;
    float* stage0 = sm + BN;
    const uint32_t stage0_u32 = smem_u32(stage0);

    const int tid = threadIdx.x;
    const int lane = tid & 31;
    const int wid = tid >> 5;
    const int wr = wid >> 2;
    const int wc = wid & 3;
    const int m0 = blockIdx.y * BM;
    const int n0 = blockIdx.x * BN;

    if (tid < BN) bias_s[tid] = bias[n0 + tid];

    const int r = lane >> 2;
    const int c = lane & 3;

    float acc[4][8][4];
#pragma unroll
    for (int mt = 0; mt < 4; mt++)
#pragma unroll
        for (int nt = 0; nt < 8; nt++)
#pragma unroll
            for (int j = 0; j < 4; j++) acc[mt][nt][j] = 0.f;

    const int T = K / BK;

    auto issue = [&](int t) {
        const uint32_t su = stage0_u32 + (uint32_t)((t & 1) * STG_FLOATS) * 4u;
#pragma unroll
        for (int i = 0; i < 4; i++) {
            const int q = tid + i * 256;
            const int row = q >> 3, qq = q & 7;
            CP_ASYNC16(su + (uint32_t)(row * ASTR + qq * 4) * 4u,
                       A + (size_t)(m0 + row) * K + t * BK + qq * 4);
        }
        const uint32_t bu = su + AS_FLOATS * 4u;
#pragma unroll
        for (int i = 0; i < 8; i++) {
            const int q = tid + i * 256;
            const int row = q >> 3, qq = q & 7;
            CP_ASYNC16(bu + (uint32_t)(row * ASTR + qq * 4) * 4u,
                       BT + (size_t)(n0 + row) * K + t * BK + qq * 4);
        }
    };

    issue(0);
    CP_COMMIT();

    for (int t = 0; t < T; t++) {
        if (t + 1 < T) {
            issue(t + 1);
            CP_COMMIT();
            CP_WAIT(1);
        } else {
            CP_WAIT(0);
        }
        __syncthreads();

        const float* As = stage0 + (t & 1) * STG_FLOATS;
        const float* Bs = As + AS_FLOATS;

#pragma unroll
        for (int kk = 0; kk < 4; kk++) {
            uint32_t af[4][4];
#pragma unroll
            for (int mt = 0; mt < 4; mt++) {
                const int mb = wr * 64 + mt * 16;
                af[mt][0] = *(const uint32_t*)&As[(mb + r) * ASTR + kk * 8 + c];
                af[mt][1] = *(const uint32_t*)&As[(mb + r + 8) * ASTR + kk * 8 + c];
                af[mt][2] = *(const uint32_t*)&As[(mb + r) * ASTR + kk * 8 + c + 4];
                af[mt][3] = *(const uint32_t*)&As[(mb + r + 8) * ASTR + kk * 8 + c + 4];
            }
            uint32_t bf[8][2];
#pragma unroll
            for (int nt = 0; nt < 8; nt++) {
                const int bn = wc * 64 + nt * 8 + r;
                bf[nt][0] = *(const uint32_t*)&Bs[bn * ASTR + kk * 8 + c];
                bf[nt][1] = *(const uint32_t*)&Bs[bn * ASTR + kk * 8 + c + 4];
            }
#pragma unroll
            for (int mt = 0; mt < 4; mt++)
#pragma unroll
                for (int nt = 0; nt < 8; nt++)
                    mma_tf32(acc[mt][nt][0], acc[mt][nt][1],
                             acc[mt][nt][2], acc[mt][nt][3],
                             af[mt][0], af[mt][1], af[mt][2], af[mt][3],
                             bf[nt][0], bf[nt][1]);
        }
        __syncthreads();
    }

#pragma unroll
    for (int mt = 0; mt < 4; mt++) {
        const int row0 = m0 + wr * 64 + mt * 16 + r;
#pragma unroll
        for (int nt = 0; nt < 8; nt++) {
            const int col = n0 + wc * 64 + nt * 8 + c * 2;
            const float bx = bias_s[wc * 64 + nt * 8 + c * 2];
            const float by = bias_s[wc * 64 + nt * 8 + c * 2 + 1];
            float v0 = acc[mt][nt][0] + bx;
            float v1 = acc[mt][nt][1] + by;
            float v2 = acc[mt][nt][2] + bx;
            float v3 = acc[mt][nt][3] + by;
            if (relu) {
                v0 = fmaxf(v0, 0.f); v1 = fmaxf(v1, 0.f);
                v2 = fmaxf(v2, 0.f); v3 = fmaxf(v3, 0.f);
            }
            if (roundout) {
                v0 = to_tf32(v0); v1 = to_tf32(v1);
                v2 = to_tf32(v2); v3 = to_tf32(v3);
            }
            *(float2*)&C[(size_t)row0 * Ntot + col] = make_float2(v0, v1);
            *(float2*)&C[(size_t)(row0 + 8) * Ntot + col] = make_float2(v2, v3);
        }
    }
}

// ---------------------------------------------------------------------------
// prep kernels
// ---------------------------------------------------------------------------
__global__ void __launch_bounds__(256) zero_uni(float* __restrict__ u)
{
    u[blockIdx.x * 256 + threadIdx.x] = 0.f;
}

__global__ void __launch_bounds__(256) cvt_x(
    const float* __restrict__ in, float* __restrict__ outp, int n4)
{
    const int i = blockIdx.x * 256 + threadIdx.x;
    if (i < n4) {
        float4 v = ((const float4*)in)[i];
        v.x = to_tf32(v.x); v.y = to_tf32(v.y);
        v.z = to_tf32(v.z); v.w = to_tf32(v.w);
        ((float4*)outp)[i] = v;
    }
}

__global__ void __launch_bounds__(256) transpose_cvt(
    const float* __restrict__ W, float* __restrict__ WT, int K, int N)
{
    __shared__ float t[32][33];
    const int bx = blockIdx.x * 32;
    const int by = blockIdx.y * 32;
    const int x = threadIdx.x & 31;
    const int y = threadIdx.x >> 5;
#pragma unroll
    for (int i = 0; i < 32; i += 8)
        t[y + i][x] = to_tf32(W[(size_t)(by + y + i) * N + bx + x]);
    __syncthreads();
#pragma unroll
    for (int i = 0; i < 32; i += 8)
        WT[(size_t)(bx + y + i) * K + by + x] = t[x][y + i];
}

// Transpose per-feature uni weights to [i][fo][fi], tf32-rounded.
__global__ void __launch_bounds__(256) uni_w_prep(
    const float* __restrict__ uw2, const float* __restrict__ uw3,
    float* __restrict__ uw2t, float* __restrict__ uw3t)
{
    __shared__ float t2[32][33];
    __shared__ float t3[32][17];
    const int i = blockIdx.x;
    const int tid = threadIdx.x;

    {
        float4 v = ((const float4*)(uw2 + (size_t)i * UH * UH))[tid];
        const int fi = tid >> 3;
        const int fo = (tid & 7) * 4;
        t2[fi][fo + 0] = to_tf32(v.x);
        t2[fi][fo + 1] = to_tf32(v.y);
        t2[fi][fo + 2] = to_tf32(v.z);
        t2[fi][fo + 3] = to_tf32(v.w);
    }
    {
        float2 v = ((const float2*)(uw3 + (size_t)i * UH * NOUT))[tid];
        const int fi = tid >> 3;
        const int fo = (tid & 7) * 2;
        t3[fi][fo + 0] = to_tf32(v.x);
        t3[fi][fo + 1] = to_tf32(v.y);
    }
    __syncthreads();
    {
        const int fo = tid >> 3;
        const int fi = (tid & 7) * 4;
        float4 o;
        o.x = t2[fi + 0][fo]; o.y = t2[fi + 1][fo];
        o.z = t2[fi + 2][fo]; o.w = t2[fi + 3][fo];
        ((float4*)(uw2t + (size_t)i * UH * UH))[tid] = o;
    }
    {
        const int fo = tid >> 4;
        const int fi = (tid & 15) * 2;
        float2 o;
        o.x = t3[fi + 0][fo]; o.y = t3[fi + 1][fo];
        ((float2*)(uw3t + (size_t)i * NOUT * UH))[tid] = o;
    }
}

// ---------------------------------------------------------------------------
// Output layer: out = h1 @ W2 + b2 + uni
// ---------------------------------------------------------------------------
__global__ void __launch_bounds__(256) gemm_out(
    const float* __restrict__ Hin, const float* __restrict__ W2,
    const float* __restrict__ b2, const float* __restrict__ uni,
    float* __restrict__ out)
{
    const int idx = blockIdx.x * 256 + threadIdx.x;
    const int b = idx >> 2;
    const int og = (idx & 3) * 4;
    const float* h = Hin + (size_t)b * HID;
    float4 acc = *(const float4*)(b2 + og);
    {
        const float4 u0 = *(const float4*)(uni + (size_t)b * NOUT + og);
        acc.x += u0.x; acc.y += u0.y; acc.z += u0.z; acc.w += u0.w;
    }
#pragma unroll 4
    for (int k = 0; k < HID; k++) {
        const float hv = h[k];
        const float4 w = *(const float4*)(W2 + k * NOUT + og);
        acc.x = fmaf(hv, w.x, acc.x);
        acc.y = fmaf(hv, w.y, acc.y);
        acc.z = fmaf(hv, w.z, acc.z);
        acc.w = fmaf(hv, w.w, acc.w);
    }
    *(float4*)(out + (size_t)b * NOUT + og) = acc;
}

// ---------------------------------------------------------------------------
// Register-resident uni MLPs: one warp = one feature, no smem/barriers in the
// mainloop. Grid (BATCH/256, NINP/8); CTA = 8 warps = 8 features x 256 rows.
// Weights live as mma fragments in registers; h2 C-frag -> A-frag via shfl.
// CTA accumulates across its 8 features in smem (stride 17, atomic), then
// merges into g_uni with global atomics.
// Launch bounds relaxed (no min-blocks): live set ~150 regs; forcing 2
// CTAs/SM would spill into the hot loop.
// ---------------------------------------------------------------------------
__global__ void __launch_bounds__(256) uni_reg(
    const float* __restrict__ xt,
    const float* __restrict__ uw1, const float* __restrict__ ub1,
    const float* __restrict__ uw2t, const float* __restrict__ ub2,
    const float* __restrict__ uw3t, const float* __restrict__ ub3,
    float* __restrict__ uni_out)
{
    __shared__ float acc_s[256 * 17];

    const int tid = threadIdx.x;
    const int lane = tid & 31;
    const int w = tid >> 5;
    const int r = lane >> 2;
    const int c = lane & 3;
    const int i = blockIdx.y * 8 + w;          // this warp's feature
    const int rowbase = blockIdx.x * 256;

#pragma unroll
    for (int q = 0; q < 17; q++) acc_s[q * 256 + tid] = 0.f;
    __syncthreads();

    // ---- per-feature weights as register fragments (one-time) ----
    uint32_t w2f[4][4][2];                     // [kk][nt][{c,c+4}]
#pragma unroll
    for (int kk = 0; kk < 4; kk++)
#pragma unroll
        for (int nt = 0; nt < 4; nt++) {
            const float* p = uw2t + (size_t)i * 1024 + (nt * 8 + r) * 32 + kk * 8 + c;
            w2f[kk][nt][0] = __float_as_uint(p[0]);
            w2f[kk][nt][1] = __float_as_uint(p[4]);
        }
    uint32_t w3f[4][2][2];
#pragma unroll
    for (int kk = 0; kk < 4; kk++)
#pragma unroll
        for (int nt = 0; nt < 2; nt++) {
            const float* p = uw3t + (size_t)i * 512 + (nt * 8 + r) * 32 + kk * 8 + c;
            w3f[kk][nt][0] = __float_as_uint(p[0]);
            w3f[kk][nt][1] = __float_as_uint(p[4]);
        }
    float w1v[8], b1v[8];
#pragma unroll
    for (int kk = 0; kk < 4; kk++) {
        w1v[kk * 2 + 0] = uw1[i * 32 + kk * 8 + c];
        w1v[kk * 2 + 1] = uw1[i * 32 + kk * 8 + c + 4];
        b1v[kk * 2 + 0] = ub1[i * 32 + kk * 8 + c];
        b1v[kk * 2 + 1] = ub1[i * 32 + kk * 8 + c + 4];
    }
    float b2v[8];
#pragma unroll
    for (int nt = 0; nt < 4; nt++) {
        b2v[nt * 2 + 0] = ub2[i * 32 + nt * 8 + 2 * c];
        b2v[nt * 2 + 1] = ub2[i * 32 + nt * 8 + 2 * c + 1];
    }
    float b3v[4];
#pragma unroll
    for (int nt = 0; nt < 2; nt++) {
        b3v[nt * 2 + 0] = ub3[i * 16 + nt * 8 + 2 * c];
        b3v[nt * 2 + 1] = ub3[i * 16 + nt * 8 + 2 * c + 1];
    }

    const int L0 = r * 4 + (c >> 1);
    const bool odd = (c & 1) != 0;

    // ---- 16 tiles of 16 rows, fully warp-independent ----
    for (int t = 0; t < 16; t++) {
        const int rb = rowbase + t * 16;

        float xl = 0.f;
        if (lane < 16) xl = xt[(size_t)i * BATCH + rb + lane];
        const float xr0 = __shfl_sync(0xffffffffu, xl, r);
        const float xr8 = __shfl_sync(0xffffffffu, xl, r + 8);

        // layer 1 -> h1 A-fragments (in registers)
        uint32_t h1f[4][4];
#pragma unroll
        for (int kk = 0; kk < 4; kk++) {
            h1f[kk][0] = tf32_bits(fmaxf(fmaf(xr0, w1v[kk * 2 + 0], b1v[kk * 2 + 0]), 0.f));
            h1f[kk][1] = tf32_bits(fmaxf(fmaf(xr8, w1v[kk * 2 + 0], b1v[kk * 2 + 0]), 0.f));
            h1f[kk][2] = tf32_bits(fmaxf(fmaf(xr0, w1v[kk * 2 + 1], b1v[kk * 2 + 1]), 0.f));
            h1f[kk][3] = tf32_bits(fmaxf(fmaf(xr8, w1v[kk * 2 + 1], b1v[kk * 2 + 1]), 0.f));
        }

        // layer 2
        float c2[4][4];
#pragma unroll
        for (int nt = 0; nt < 4; nt++)
#pragma unroll
            for (int q = 0; q < 4; q++) c2[nt][q] = 0.f;
#pragma unroll
        for (int kk = 0; kk < 4; kk++)
#pragma unroll
            for (int nt = 0; nt < 4; nt++)
                mma_tf32(c2[nt][0], c2[nt][1], c2[nt][2], c2[nt][3],
                         h1f[kk][0], h1f[kk][1], h1f[kk][2], h1f[kk][3],
                         w2f[kk][nt][0], w2f[kk][nt][1]);

        // h2 = tf32(relu(c2 + b2)) as C-fragments
        uint32_t h2r[4][4];
#pragma unroll
        for (int nt = 0; nt < 4; nt++) {
            h2r[nt][0] = tf32_bits(fmaxf(c2[nt][0] + b2v[nt * 2 + 0], 0.f));
            h2r[nt][1] = tf32_bits(fmaxf(c2[nt][1] + b2v[nt * 2 + 1], 0.f));
            h2r[nt][2] = tf32_bits(fmaxf(c2[nt][2] + b2v[nt * 2 + 0], 0.f));
            h2r[nt][3] = tf32_bits(fmaxf(c2[nt][3] + b2v[nt * 2 + 1], 0.f));
        }

        // C-frag -> A-frag via shuffles (col kk*8+c held by lane r*4+(c>>1),
        // reg parity c&1; col kk*8+c+4 by lane +2, same parity)
        uint32_t h2a[4][4];
#pragma unroll
        for (int kk = 0; kk < 4; kk++) {
            const uint32_t e0 = __shfl_sync(0xffffffffu, h2r[kk][0], L0);
            const uint32_t o0 = __shfl_sync(0xffffffffu, h2r[kk][1], L0);
            const uint32_t e8 = __shfl_sync(0xffffffffu, h2r[kk][2], L0);
            const uint32_t o8 = __shfl_sync(0xffffffffu, h2r[kk][3], L0);
            const uint32_t f0 = __shfl_sync(0xffffffffu, h2r[kk][0], L0 + 2);
            const uint32_t p0 = __shfl_sync(0xffffffffu, h2r[kk][1], L0 + 2);
            const uint32_t f8 = __shfl_sync(0xffffffffu, h2r[kk][2], L0 + 2);
            const uint32_t p8 = __shfl_sync(0xffffffffu, h2r[kk][3], L0 + 2);
            h2a[kk][0] = odd ? o0 : e0;
            h2a[kk][1] = odd ? o8 : e8;
            h2a[kk][2] = odd ? p0 : f0;
            h2a[kk][3] = odd ? p8 : f8;
        }

        // layer 3 (accumulators seeded with b3)
        float u[2][4];
#pragma unroll
        for (int nt = 0; nt < 2; nt++) {
            u[nt][0] = b3v[nt * 2 + 0];
            u[nt][1] = b3v[nt * 2 + 1];
            u[nt][2] = b3v[nt * 2 + 0];
            u[nt][3] = b3v[nt * 2 + 1];
        }
#pragma unroll
        for (int kk = 0; kk < 4; kk++)
#pragma unroll
            for (int nt = 0; nt < 2; nt++)
                mma_tf32(u[nt][0], u[nt][1], u[nt][2], u[nt][3],
                         h2a[kk][0], h2a[kk][1], h2a[kk][2], h2a[kk][3],
                         w3f[kk][nt][0], w3f[kk][nt][1]);

        // accumulate into CTA smem (8 features race -> atomic, stride 17)
        const int lr0 = t * 16 + r;
#pragma unroll
        for (int nt = 0; nt < 2; nt++) {
            const int col = nt * 8 + 2 * c;
            atomicAdd(&acc_s[lr0 * 17 + col],           u[nt][0]);
            atomicAdd(&acc_s[lr0 * 17 + col + 1],       u[nt][1]);
            atomicAdd(&acc_s[(lr0 + 8) * 17 + col],     u[nt][2]);
            atomicAdd(&acc_s[(lr0 + 8) * 17 + col + 1], u[nt][3]);
        }
    }

    __syncthreads();
    // merge CTA accumulator into global (chunks race -> global atomics)
#pragma unroll
    for (int q = 0; q < 16; q++) {
        const int idx = q * 256 + tid;
        const int row = idx >> 4, col = idx & 15;
        atomicAdd(&uni_out[(size_t)(rowbase + row) * NOUT + col],
                  acc_s[row * 17 + col]);
    }
}

// ---------------------------------------------------------------------------
extern "C" void kernel_launch(void* const* d_in, const int* in_sizes, int n_in,
                              void* d_out, int out_size)
{
    const float* x   = (const float*)d_in[0];
    const float* W0  = (const float*)d_in[1];
    const float* b0  = (const float*)d_in[2];
    const float* W1  = (const float*)d_in[3];
    const float* b1  = (const float*)d_in[4];
    const float* W2  = (const float*)d_in[5];
    const float* b2  = (const float*)d_in[6];
    const float* uw1 = (const float*)d_in[7];
    const float* ub1 = (const float*)d_in[8];
    const float* uw2 = (const float*)d_in[9];
    const float* ub2 = (const float*)d_in[10];
    const float* uw3 = (const float*)d_in[11];
    const float* ub3 = (const float*)d_in[12];
    float* out = (float*)d_out;

    float *h0, *h1, *xr, *xt, *w0t, *w1t, *uw2t, *uw3t, *uni;
    cudaGetSymbolAddress((void**)&h0, g_h0);
    cudaGetSymbolAddress((void**)&h1, g_h1);
    cudaGetSymbolAddress((void**)&xr, g_x);
    cudaGetSymbolAddress((void**)&xt, g_xt);
    cudaGetSymbolAddress((void**)&w0t, g_w0t);
    cudaGetSymbolAddress((void**)&w1t, g_w1t);
    cudaGetSymbolAddress((void**)&uw2t, g_uw2t);
    cudaGetSymbolAddress((void**)&uw3t, g_uw3t);
    cudaGetSymbolAddress((void**)&uni, g_uni);

    cudaFuncSetAttribute(mma_gemm, cudaFuncAttributeMaxDynamicSharedMemorySize, GEMM_SMEM);

    // uni path first (slot 3 = profiler capture window)
    uni_w_prep<<<NINP, 256>>>(uw2, uw3, uw2t, uw3t);                     // 0
    {
        dim3 gx(NINP / 32, BATCH / 32);
        transpose_cvt<<<gx, 256>>>(x, xt, BATCH, NINP);                  // 1
    }
    zero_uni<<<BATCH * NOUT / 256, 256>>>(uni);                          // 2
    {
        dim3 grid(BATCH / 256, NINP / 8);
        uni_reg<<<grid, 256>>>(xt, uw1, ub1, uw2t, ub2, uw3t, ub3, uni); // 3
    }

    // main MLP
    cvt_x<<<(BATCH * NINP / 4 + 255) / 256, 256>>>(x, xr, BATCH * NINP / 4);
    {
        dim3 g0(HID / 32, NINP / 32);
        transpose_cvt<<<g0, 256>>>(W0, w0t, NINP, HID);
        dim3 g1(HID / 32, HID / 32);
        transpose_cvt<<<g1, 256>>>(W1, w1t, HID, HID);
    }
    {
        dim3 grid(HID / BN, BATCH / BM);
        mma_gemm<<<grid, 256, GEMM_SMEM>>>(xr, w0t, b0, h0, NINP, HID, 1, 1);
        mma_gemm<<<grid, 256, GEMM_SMEM>>>(h0, w1t, b1, h1, HID, HID, 1, 0);
    }

    // out = h1 @ W2 + b2 + uni
    gemm_out<<<(BATCH * 4) / 256, 256>>>(h1, W2, b2, uni, out);
}

// round 13
// speedup vs baseline: 2.8214x; 1.1898x over previous
#include <cuda_runtime.h>
#include <cstdint>

#define BATCH 16384
#define NINP  256
#define HID   1024
#define NOUT  16
#define UH    32

// ---------------------------------------------------------------------------
// Device scratch (no runtime allocation allowed)
// ---------------------------------------------------------------------------
__device__ float g_h0[BATCH * HID];
__device__ float g_h1[BATCH * HID];
__device__ float g_x[BATCH * NINP];    // x pre-rounded to tf32 (main GEMM A)
__device__ float g_xt[NINP * BATCH];   // x^T, tf32-rounded (uni layer-1 input)
__device__ float g_w0t[HID * NINP];    // W0^T [HID][NINP], tf32-rounded
__device__ float g_w1t[HID * HID];     // W1^T, tf32-rounded
__device__ float g_w2t[NOUT * HID];    // W2^T [16][1024], tf32-rounded
__device__ float g_uw2t[NINP * UH * UH];    // per-feature w2^T [i][fo][fi], tf32
__device__ float g_uw3t[NINP * UH * NOUT];  // per-feature w3^T [i][fo][fi], tf32
__device__ float g_uni[BATCH * NOUT];       // uni sums (zeroed, atomic merge)

// ---------------------------------------------------------------------------
// Helpers
// ---------------------------------------------------------------------------
__device__ __forceinline__ uint32_t smem_u32(const void* p) {
    uint32_t a;
    asm("{ .reg .u64 t; cvta.to.shared.u64 t, %1; cvt.u32.u64 %0, t; }"
        : "=r"(a) : "l"(p));
    return a;
}

// tf32 destination is a .b32 register (storage format), per PTX ISA.
__device__ __forceinline__ float to_tf32(float x) {
    uint32_t r;
    asm("cvt.rna.tf32.f32 %0, %1;" : "=r"(r) : "f"(x));
    return __uint_as_float(r);
}
__device__ __forceinline__ uint32_t tf32_bits(float x) {
    uint32_t r;
    asm("cvt.rna.tf32.f32 %0, %1;" : "=r"(r) : "f"(x));
    return r;
}

#define CP_ASYNC16(dst_u32, src_ptr) \
    asm volatile("cp.async.cg.shared.global [%0], [%1], 16;" \
        :: "r"(dst_u32), "l"(src_ptr))
#define CP_COMMIT() asm volatile("cp.async.commit_group;")
#define CP_WAIT(n)  asm volatile("cp.async.wait_group %0;" :: "n"(n))

__device__ __forceinline__ void mma_tf32(
    float& d0, float& d1, float& d2, float& d3,
    uint32_t a0, uint32_t a1, uint32_t a2, uint32_t a3,
    uint32_t b0, uint32_t b1)
{
    asm volatile(
        "mma.sync.aligned.m16n8k8.row.col.f32.tf32.tf32.f32 "
        "{%0,%1,%2,%3}, {%4,%5,%6,%7}, {%8,%9}, {%0,%1,%2,%3};"
        : "+f"(d0), "+f"(d1), "+f"(d2), "+f"(d3)
        : "r"(a0), "r"(a1), "r"(a2), "r"(a3), "r"(b0), "r"(b1));
}

// ---------------------------------------------------------------------------
// tf32 mma.sync GEMM (unchanged — measured 78us on GEMM1)
// ---------------------------------------------------------------------------
#define BM 128
#define BN 256
#define BK 32
#define ASTR 36
#define AS_FLOATS (BM * ASTR)
#define BS_FLOATS (BN * ASTR)
#define STG_FLOATS (AS_FLOATS + BS_FLOATS)
#define GEMM_SMEM ((BN + 2 * STG_FLOATS) * 4)

__global__ void __launch_bounds__(256, 1) mma_gemm(
    const float* __restrict__ A, const float* __restrict__ BT,
    const float* __restrict__ bias, float* __restrict__ C,
    int K, int Ntot, int relu, int roundout)
{
    extern __shared__ float sm[];
    float* bias_s = sm;
    float* stage0 = sm + BN;
    const uint32_t stage0_u32 = smem_u32(stage0);

    const int tid = threadIdx.x;
    const int lane = tid & 31;
    const int wid = tid >> 5;
    const int wr = wid >> 2;
    const int wc = wid & 3;
    const int m0 = blockIdx.y * BM;
    const int n0 = blockIdx.x * BN;

    if (tid < BN) bias_s[tid] = bias[n0 + tid];

    const int r = lane >> 2;
    const int c = lane & 3;

    float acc[4][8][4];
#pragma unroll
    for (int mt = 0; mt < 4; mt++)
#pragma unroll
        for (int nt = 0; nt < 8; nt++)
#pragma unroll
            for (int j = 0; j < 4; j++) acc[mt][nt][j] = 0.f;

    const int T = K / BK;

    auto issue = [&](int t) {
        const uint32_t su = stage0_u32 + (uint32_t)((t & 1) * STG_FLOATS) * 4u;
#pragma unroll
        for (int i = 0; i < 4; i++) {
            const int q = tid + i * 256;
            const int row = q >> 3, qq = q & 7;
            CP_ASYNC16(su + (uint32_t)(row * ASTR + qq * 4) * 4u,
                       A + (size_t)(m0 + row) * K + t * BK + qq * 4);
        }
        const uint32_t bu = su + AS_FLOATS * 4u;
#pragma unroll
        for (int i = 0; i < 8; i++) {
            const int q = tid + i * 256;
            const int row = q >> 3, qq = q & 7;
            CP_ASYNC16(bu + (uint32_t)(row * ASTR + qq * 4) * 4u,
                       BT + (size_t)(n0 + row) * K + t * BK + qq * 4);
        }
    };

    issue(0);
    CP_COMMIT();

    for (int t = 0; t < T; t++) {
        if (t + 1 < T) {
            issue(t + 1);
            CP_COMMIT();
            CP_WAIT(1);
        } else {
            CP_WAIT(0);
        }
        __syncthreads();

        const float* As = stage0 + (t & 1) * STG_FLOATS;
        const float* Bs = As + AS_FLOATS;

#pragma unroll
        for (int kk = 0; kk < 4; kk++) {
            uint32_t af[4][4];
#pragma unroll
            for (int mt = 0; mt < 4; mt++) {
                const int mb = wr * 64 + mt * 16;
                af[mt][0] = *(const uint32_t*)&As[(mb + r) * ASTR + kk * 8 + c];
                af[mt][1] = *(const uint32_t*)&As[(mb + r + 8) * ASTR + kk * 8 + c];
                af[mt][2] = *(const uint32_t*)&As[(mb + r) * ASTR + kk * 8 + c + 4];
                af[mt][3] = *(const uint32_t*)&As[(mb + r + 8) * ASTR + kk * 8 + c + 4];
            }
            uint32_t bf[8][2];
#pragma unroll
            for (int nt = 0; nt < 8; nt++) {
                const int bn = wc * 64 + nt * 8 + r;
                bf[nt][0] = *(const uint32_t*)&Bs[bn * ASTR + kk * 8 + c];
                bf[nt][1] = *(const uint32_t*)&Bs[bn * ASTR + kk * 8 + c + 4];
            }
#pragma unroll
            for (int mt = 0; mt < 4; mt++)
#pragma unroll
                for (int nt = 0; nt < 8; nt++)
                    mma_tf32(acc[mt][nt][0], acc[mt][nt][1],
                             acc[mt][nt][2], acc[mt][nt][3],
                             af[mt][0], af[mt][1], af[mt][2], af[mt][3],
                             bf[nt][0], bf[nt][1]);
        }
        __syncthreads();
    }

#pragma unroll
    for (int mt = 0; mt < 4; mt++) {
        const int row0 = m0 + wr * 64 + mt * 16 + r;
#pragma unroll
        for (int nt = 0; nt < 8; nt++) {
            const int col = n0 + wc * 64 + nt * 8 + c * 2;
            const float bx = bias_s[wc * 64 + nt * 8 + c * 2];
            const float by = bias_s[wc * 64 + nt * 8 + c * 2 + 1];
            float v0 = acc[mt][nt][0] + bx;
            float v1 = acc[mt][nt][1] + by;
            float v2 = acc[mt][nt][2] + bx;
            float v3 = acc[mt][nt][3] + by;
            if (relu) {
                v0 = fmaxf(v0, 0.f); v1 = fmaxf(v1, 0.f);
                v2 = fmaxf(v2, 0.f); v3 = fmaxf(v3, 0.f);
            }
            if (roundout) {
                v0 = to_tf32(v0); v1 = to_tf32(v1);
                v2 = to_tf32(v2); v3 = to_tf32(v3);
            }
            *(float2*)&C[(size_t)row0 * Ntot + col] = make_float2(v0, v1);
            *(float2*)&C[(size_t)(row0 + 8) * Ntot + col] = make_float2(v2, v3);
        }
    }
}

// ---------------------------------------------------------------------------
// mma_out: out[16384,16] = h1[16384,1024] @ W2 + b2 + uni   (tensor-core thin GEMM)
// CTA = 128 rows, 8 warps (warp = m16, nt=2 covers all 16 cols), K chunks of 32
// double-buffered via cp.async. h1 read once, coalesced.
// ---------------------------------------------------------------------------
#define OB_A_FLOATS (128 * ASTR)           // 4608
#define OB_B_FLOATS (16 * ASTR)            // 576
#define OB_STG (OB_A_FLOATS + OB_B_FLOATS) // 5184
#define OUT_SMEM (2 * OB_STG * 4)          // 41472 B

__global__ void __launch_bounds__(256, 1) mma_out(
    const float* __restrict__ Hin, const float* __restrict__ W2T,
    const float* __restrict__ b2, const float* __restrict__ uni,
    float* __restrict__ out)
{
    extern __shared__ float sm[];
    const uint32_t sm_u32 = smem_u32(sm);

    const int tid = threadIdx.x;
    const int lane = tid & 31;
    const int w = tid >> 5;
    const int r = lane >> 2;
    const int c = lane & 3;
    const int m0 = blockIdx.x * 128;

    auto issue = [&](int t) {
        const uint32_t su = sm_u32 + (uint32_t)((t & 1) * OB_STG) * 4u;
#pragma unroll
        for (int i = 0; i < 4; i++) {                 // A: 128 rows x 8 quads
            const int q = tid + i * 256;
            const int row = q >> 3, qq = q & 7;
            CP_ASYNC16(su + (uint32_t)(row * ASTR + qq * 4) * 4u,
                       Hin + (size_t)(m0 + row) * HID + t * BK + qq * 4);
        }
        if (tid < 128) {                              // B: 16 rows x 8 quads
            const int row = tid >> 3, qq = tid & 7;
            CP_ASYNC16(su + (uint32_t)(OB_A_FLOATS + row * ASTR + qq * 4) * 4u,
                       W2T + (size_t)row * HID + t * BK + qq * 4);
        }
    };

    float acc[2][4];
#pragma unroll
    for (int nt = 0; nt < 2; nt++)
#pragma unroll
        for (int q = 0; q < 4; q++) acc[nt][q] = 0.f;

    issue(0);
    CP_COMMIT();

    const int T = HID / BK;                           // 32
    for (int t = 0; t < T; t++) {
        if (t + 1 < T) {
            issue(t + 1);
            CP_COMMIT();
            CP_WAIT(1);
        } else {
            CP_WAIT(0);
        }
        __syncthreads();

        const float* As = sm + (t & 1) * OB_STG;
        const float* Bs = As + OB_A_FLOATS;
        const int mb = 16 * w;

#pragma unroll
        for (int kk = 0; kk < 4; kk++) {
            const uint32_t a0 = *(const uint32_t*)&As[(mb + r) * ASTR + kk * 8 + c];
            const uint32_t a1 = *(const uint32_t*)&As[(mb + r + 8) * ASTR + kk * 8 + c];
            const uint32_t a2 = *(const uint32_t*)&As[(mb + r) * ASTR + kk * 8 + c + 4];
            const uint32_t a3 = *(const uint32_t*)&As[(mb + r + 8) * ASTR + kk * 8 + c + 4];
#pragma unroll
            for (int nt = 0; nt < 2; nt++) {
                const uint32_t b0 = *(const uint32_t*)&Bs[(nt * 8 + r) * ASTR + kk * 8 + c];
                const uint32_t b1 = *(const uint32_t*)&Bs[(nt * 8 + r) * ASTR + kk * 8 + c + 4];
                mma_tf32(acc[nt][0], acc[nt][1], acc[nt][2], acc[nt][3],
                         a0, a1, a2, a3, b0, b1);
            }
        }
        __syncthreads();
    }

    // epilogue: + b2 + uni, float2 stores
    const int row0 = m0 + 16 * w + r;
#pragma unroll
    for (int nt = 0; nt < 2; nt++) {
        const int col = nt * 8 + 2 * c;
        const float bx = b2[col], by = b2[col + 1];
        const float2 u0 = *(const float2*)&uni[(size_t)row0 * NOUT + col];
        const float2 u1 = *(const float2*)&uni[(size_t)(row0 + 8) * NOUT + col];
        *(float2*)&out[(size_t)row0 * NOUT + col] =
            make_float2(acc[nt][0] + bx + u0.x, acc[nt][1] + by + u0.y);
        *(float2*)&out[(size_t)(row0 + 8) * NOUT + col] =
            make_float2(acc[nt][2] + bx + u1.x, acc[nt][3] + by + u1.y);
    }
}

// ---------------------------------------------------------------------------
// prep kernels
// ---------------------------------------------------------------------------
__global__ void __launch_bounds__(256) zero_uni(float* __restrict__ u)
{
    u[blockIdx.x * 256 + threadIdx.x] = 0.f;
}

__global__ void __launch_bounds__(256) cvt_x(
    const float* __restrict__ in, float* __restrict__ outp, int n4)
{
    const int i = blockIdx.x * 256 + threadIdx.x;
    if (i < n4) {
        float4 v = ((const float4*)in)[i];
        v.x = to_tf32(v.x); v.y = to_tf32(v.y);
        v.z = to_tf32(v.z); v.w = to_tf32(v.w);
        ((float4*)outp)[i] = v;
    }
}

__global__ void __launch_bounds__(256) transpose_cvt(
    const float* __restrict__ W, float* __restrict__ WT, int K, int N)
{
    __shared__ float t[32][33];
    const int bx = blockIdx.x * 32;
    const int by = blockIdx.y * 32;
    const int x = threadIdx.x & 31;
    const int y = threadIdx.x >> 5;
#pragma unroll
    for (int i = 0; i < 32; i += 8)
        t[y + i][x] = to_tf32(W[(size_t)(by + y + i) * N + bx + x]);
    __syncthreads();
#pragma unroll
    for (int i = 0; i < 32; i += 8)
        WT[(size_t)(bx + y + i) * K + by + x] = t[x][y + i];
}

// W2 [1024][16] -> W2^T [16][1024] (tf32)
__global__ void __launch_bounds__(256) w2t_prep(
    const float* __restrict__ W2, float* __restrict__ W2T)
{
    const int idx = blockIdx.x * 256 + threadIdx.x;   // 16384 total
    const int k = idx >> 4, o = idx & 15;
    W2T[(size_t)o * HID + k] = to_tf32(W2[(size_t)k * NOUT + o]);
}

// Transpose per-feature uni weights to [i][fo][fi], tf32-rounded.
__global__ void __launch_bounds__(256) uni_w_prep(
    const float* __restrict__ uw2, const float* __restrict__ uw3,
    float* __restrict__ uw2t, float* __restrict__ uw3t)
{
    __shared__ float t2[32][33];
    __shared__ float t3[32][17];
    const int i = blockIdx.x;
    const int tid = threadIdx.x;

    {
        float4 v = ((const float4*)(uw2 + (size_t)i * UH * UH))[tid];
        const int fi = tid >> 3;
        const int fo = (tid & 7) * 4;
        t2[fi][fo + 0] = to_tf32(v.x);
        t2[fi][fo + 1] = to_tf32(v.y);
        t2[fi][fo + 2] = to_tf32(v.z);
        t2[fi][fo + 3] = to_tf32(v.w);
    }
    {
        float2 v = ((const float2*)(uw3 + (size_t)i * UH * NOUT))[tid];
        const int fi = tid >> 3;
        const int fo = (tid & 7) * 2;
        t3[fi][fo + 0] = to_tf32(v.x);
        t3[fi][fo + 1] = to_tf32(v.y);
    }
    __syncthreads();
    {
        const int fo = tid >> 3;
        const int fi = (tid & 7) * 4;
        float4 o;
        o.x = t2[fi + 0][fo]; o.y = t2[fi + 1][fo];
        o.z = t2[fi + 2][fo]; o.w = t2[fi + 3][fo];
        ((float4*)(uw2t + (size_t)i * UH * UH))[tid] = o;
    }
    {
        const int fo = tid >> 4;
        const int fi = (tid & 15) * 2;
        float2 o;
        o.x = t3[fi + 0][fo]; o.y = t3[fi + 1][fo];
        ((float2*)(uw3t + (size_t)i * NOUT * UH))[tid] = o;
    }
}

// ---------------------------------------------------------------------------
// Register-resident uni MLPs (R12-measured 205us)
// ---------------------------------------------------------------------------
__global__ void __launch_bounds__(256) uni_reg(
    const float* __restrict__ xt,
    const float* __restrict__ uw1, const float* __restrict__ ub1,
    const float* __restrict__ uw2t, const float* __restrict__ ub2,
    const float* __restrict__ uw3t, const float* __restrict__ ub3,
    float* __restrict__ uni_out)
{
    __shared__ float acc_s[256 * 17];

    const int tid = threadIdx.x;
    const int lane = tid & 31;
    const int w = tid >> 5;
    const int r = lane >> 2;
    const int c = lane & 3;
    const int i = blockIdx.y * 8 + w;          // this warp's feature
    const int rowbase = blockIdx.x * 256;

#pragma unroll
    for (int q = 0; q < 17; q++) acc_s[q * 256 + tid] = 0.f;
    __syncthreads();

    uint32_t w2f[4][4][2];
#pragma unroll
    for (int kk = 0; kk < 4; kk++)
#pragma unroll
        for (int nt = 0; nt < 4; nt++) {
            const float* p = uw2t + (size_t)i * 1024 + (nt * 8 + r) * 32 + kk * 8 + c;
            w2f[kk][nt][0] = __float_as_uint(p[0]);
            w2f[kk][nt][1] = __float_as_uint(p[4]);
        }
    uint32_t w3f[4][2][2];
#pragma unroll
    for (int kk = 0; kk < 4; kk++)
#pragma unroll
        for (int nt = 0; nt < 2; nt++) {
            const float* p = uw3t + (size_t)i * 512 + (nt * 8 + r) * 32 + kk * 8 + c;
            w3f[kk][nt][0] = __float_as_uint(p[0]);
            w3f[kk][nt][1] = __float_as_uint(p[4]);
        }
    float w1v[8], b1v[8];
#pragma unroll
    for (int kk = 0; kk < 4; kk++) {
        w1v[kk * 2 + 0] = uw1[i * 32 + kk * 8 + c];
        w1v[kk * 2 + 1] = uw1[i * 32 + kk * 8 + c + 4];
        b1v[kk * 2 + 0] = ub1[i * 32 + kk * 8 + c];
        b1v[kk * 2 + 1] = ub1[i * 32 + kk * 8 + c + 4];
    }
    float b2v[8];
#pragma unroll
    for (int nt = 0; nt < 4; nt++) {
        b2v[nt * 2 + 0] = ub2[i * 32 + nt * 8 + 2 * c];
        b2v[nt * 2 + 1] = ub2[i * 32 + nt * 8 + 2 * c + 1];
    }
    float b3v[4];
#pragma unroll
    for (int nt = 0; nt < 2; nt++) {
        b3v[nt * 2 + 0] = ub3[i * 16 + nt * 8 + 2 * c];
        b3v[nt * 2 + 1] = ub3[i * 16 + nt * 8 + 2 * c + 1];
    }

    const int L0 = r * 4 + (c >> 1);
    const bool odd = (c & 1) != 0;

    for (int t = 0; t < 16; t++) {
        const int rb = rowbase + t * 16;

        float xl = 0.f;
        if (lane < 16) xl = xt[(size_t)i * BATCH + rb + lane];
        const float xr0 = __shfl_sync(0xffffffffu, xl, r);
        const float xr8 = __shfl_sync(0xffffffffu, xl, r + 8);

        uint32_t h1f[4][4];
#pragma unroll
        for (int kk = 0; kk < 4; kk++) {
            h1f[kk][0] = tf32_bits(fmaxf(fmaf(xr0, w1v[kk * 2 + 0], b1v[kk * 2 + 0]), 0.f));
            h1f[kk][1] = tf32_bits(fmaxf(fmaf(xr8, w1v[kk * 2 + 0], b1v[kk * 2 + 0]), 0.f));
            h1f[kk][2] = tf32_bits(fmaxf(fmaf(xr0, w1v[kk * 2 + 1], b1v[kk * 2 + 1]), 0.f));
            h1f[kk][3] = tf32_bits(fmaxf(fmaf(xr8, w1v[kk * 2 + 1], b1v[kk * 2 + 1]), 0.f));
        }

        float c2[4][4];
#pragma unroll
        for (int nt = 0; nt < 4; nt++)
#pragma unroll
            for (int q = 0; q < 4; q++) c2[nt][q] = 0.f;
#pragma unroll
        for (int kk = 0; kk < 4; kk++)
#pragma unroll
            for (int nt = 0; nt < 4; nt++)
                mma_tf32(c2[nt][0], c2[nt][1], c2[nt][2], c2[nt][3],
                         h1f[kk][0], h1f[kk][1], h1f[kk][2], h1f[kk][3],
                         w2f[kk][nt][0], w2f[kk][nt][1]);

        uint32_t h2r[4][4];
#pragma unroll
        for (int nt = 0; nt < 4; nt++) {
            h2r[nt][0] = tf32_bits(fmaxf(c2[nt][0] + b2v[nt * 2 + 0], 0.f));
            h2r[nt][1] = tf32_bits(fmaxf(c2[nt][1] + b2v[nt * 2 + 1], 0.f));
            h2r[nt][2] = tf32_bits(fmaxf(c2[nt][2] + b2v[nt * 2 + 0], 0.f));
            h2r[nt][3] = tf32_bits(fmaxf(c2[nt][3] + b2v[nt * 2 + 1], 0.f));
        }

        uint32_t h2a[4][4];
#pragma unroll
        for (int kk = 0; kk < 4; kk++) {
            const uint32_t e0 = __shfl_sync(0xffffffffu, h2r[kk][0], L0);
            const uint32_t o0 = __shfl_sync(0xffffffffu, h2r[kk][1], L0);
            const uint32_t e8 = __shfl_sync(0xffffffffu, h2r[kk][2], L0);
            const uint32_t o8 = __shfl_sync(0xffffffffu, h2r[kk][3], L0);
            const uint32_t f0 = __shfl_sync(0xffffffffu, h2r[kk][0], L0 + 2);
            const uint32_t p0 = __shfl_sync(0xffffffffu, h2r[kk][1], L0 + 2);
            const uint32_t f8 = __shfl_sync(0xffffffffu, h2r[kk][2], L0 + 2);
            const uint32_t p8 = __shfl_sync(0xffffffffu, h2r[kk][3], L0 + 2);
            h2a[kk][0] = odd ? o0 : e0;
            h2a[kk][1] = odd ? o8 : e8;
            h2a[kk][2] = odd ? p0 : f0;
            h2a[kk][3] = odd ? p8 : f8;
        }

        float u[2][4];
#pragma unroll
        for (int nt = 0; nt < 2; nt++) {
            u[nt][0] = b3v[nt * 2 + 0];
            u[nt][1] = b3v[nt * 2 + 1];
            u[nt][2] = b3v[nt * 2 + 0];
            u[nt][3] = b3v[nt * 2 + 1];
        }
#pragma unroll
        for (int kk = 0; kk < 4; kk++)
#pragma unroll
            for (int nt = 0; nt < 2; nt++)
                mma_tf32(u[nt][0], u[nt][1], u[nt][2], u[nt][3],
                         h2a[kk][0], h2a[kk][1], h2a[kk][2], h2a[kk][3],
                         w3f[kk][nt][0], w3f[kk][nt][1]);

        const int lr0 = t * 16 + r;
#pragma unroll
        for (int nt = 0; nt < 2; nt++) {
            const int col = nt * 8 + 2 * c;
            atomicAdd(&acc_s[lr0 * 17 + col],           u[nt][0]);
            atomicAdd(&acc_s[lr0 * 17 + col + 1],       u[nt][1]);
            atomicAdd(&acc_s[(lr0 + 8) * 17 + col],     u[nt][2]);
            atomicAdd(&acc_s[(lr0 + 8) * 17 + col + 1], u[nt][3]);
        }
    }

    __syncthreads();
#pragma unroll
    for (int q = 0; q < 16; q++) {
        const int idx = q * 256 + tid;
        const int row = idx >> 4, col = idx & 15;
        atomicAdd(&uni_out[(size_t)(rowbase + row) * NOUT + col],
                  acc_s[row * 17 + col]);
    }
}

// ---------------------------------------------------------------------------
extern "C" void kernel_launch(void* const* d_in, const int* in_sizes, int n_in,
                              void* d_out, int out_size)
{
    const float* x   = (const float*)d_in[0];
    const float* W0  = (const float*)d_in[1];
    const float* b0  = (const float*)d_in[2];
    const float* W1  = (const float*)d_in[3];
    const float* b1  = (const float*)d_in[4];
    const float* W2  = (const float*)d_in[5];
    const float* b2  = (const float*)d_in[6];
    const float* uw1 = (const float*)d_in[7];
    const float* ub1 = (const float*)d_in[8];
    const float* uw2 = (const float*)d_in[9];
    const float* ub2 = (const float*)d_in[10];
    const float* uw3 = (const float*)d_in[11];
    const float* ub3 = (const float*)d_in[12];
    float* out = (float*)d_out;

    float *h0, *h1, *xr, *xt, *w0t, *w1t, *w2t, *uw2t, *uw3t, *uni;
    cudaGetSymbolAddress((void**)&h0, g_h0);
    cudaGetSymbolAddress((void**)&h1, g_h1);
    cudaGetSymbolAddress((void**)&xr, g_x);
    cudaGetSymbolAddress((void**)&xt, g_xt);
    cudaGetSymbolAddress((void**)&w0t, g_w0t);
    cudaGetSymbolAddress((void**)&w1t, g_w1t);
    cudaGetSymbolAddress((void**)&w2t, g_w2t);
    cudaGetSymbolAddress((void**)&uw2t, g_uw2t);
    cudaGetSymbolAddress((void**)&uw3t, g_uw3t);
    cudaGetSymbolAddress((void**)&uni, g_uni);

    cudaFuncSetAttribute(mma_gemm, cudaFuncAttributeMaxDynamicSharedMemorySize, GEMM_SMEM);
    cudaFuncSetAttribute(mma_out, cudaFuncAttributeMaxDynamicSharedMemorySize, OUT_SMEM);

    // uni path first (slot 3 = profiler capture window)
    uni_w_prep<<<NINP, 256>>>(uw2, uw3, uw2t, uw3t);                     // 0
    {
        dim3 gx(NINP / 32, BATCH / 32);
        transpose_cvt<<<gx, 256>>>(x, xt, BATCH, NINP);                  // 1
    }
    zero_uni<<<BATCH * NOUT / 256, 256>>>(uni);                          // 2
    {
        dim3 grid(BATCH / 256, NINP / 8);
        uni_reg<<<grid, 256>>>(xt, uw1, ub1, uw2t, ub2, uw3t, ub3, uni); // 3
    }

    // main MLP
    cvt_x<<<(BATCH * NINP / 4 + 255) / 256, 256>>>(x, xr, BATCH * NINP / 4);
    {
        dim3 g0(HID / 32, NINP / 32);
        transpose_cvt<<<g0, 256>>>(W0, w0t, NINP, HID);
        dim3 g1(HID / 32, HID / 32);
        transpose_cvt<<<g1, 256>>>(W1, w1t, HID, HID);
    }
    w2t_prep<<<NOUT * HID / 256, 256>>>(W2, w2t);
    {
        dim3 grid(HID / BN, BATCH / BM);
        mma_gemm<<<grid, 256, GEMM_SMEM>>>(xr, w0t, b0, h0, NINP, HID, 1, 1);
        // roundout=1: h1 feeds the tf32 mma_out
        mma_gemm<<<grid, 256, GEMM_SMEM>>>(h0, w1t, b1, h1, HID, HID, 1, 1);
    }

    // out = h1 @ W2 + b2 + uni (tensor-core thin GEMM)
    mma_out<<<BATCH / 128, 256, OUT_SMEM>>>(h1, w2t, b2, uni, out);
}